// round 3
// baseline (speedup 1.0000x reference)
#include <cuda_runtime.h>
#include <cstdint>
#include <cstddef>

// Problem constants
#define S     1024
#define D     512
#define NH    8
#define HD    64
#define BATCH 8
#define BS    (BATCH * S)      // 8192 rows

// GEMM tile config: 64x64 tile, BK=16, 256 threads, 4x4 per thread
#define BM 64
#define BN 64
#define BK 16

#define MASK_ELEMS (BATCH * S * S)   // 8,388,608

// ---------------------------------------------------------------------------
// Scratch (static device globals -- no allocations allowed in kernel_launch)
// ---------------------------------------------------------------------------
__device__ float g_Q[BS * D];       // q @ Wq.T + bq           (16 MB)
__device__ float g_Kp[BS * D];      // k @ Wk.T + bk
__device__ float g_Vp[BS * D];      // v @ Wv.T + bv
__device__ float g_Pp[BS * D];      // pos_emb @ Wpos.T
__device__ float g_ctx[BS * D];     // attn @ V (pre out-proj)
__device__ float g_pos[67108864];   // raw pos scores [B,H,S,S] (256 MB)
__device__ uchar4 g_mask4[MASK_ELEMS / 4];   // normalized mask (u8 0/1)
__device__ unsigned g_mask_kind;    // 0 = u8/bool, 1 = int32, 2 = float32

// ---------------------------------------------------------------------------
// Mask dtype detection: scan first 64K words of the raw mask buffer.
//   float32 mask: words are 0x00000000 / 0x3F800000
//   u8 bool mask: bytes are 0x00/0x01 -> many words with 0x01 in lanes 1..3
//   int32 mask  : words are 0 / 1 only
// ---------------------------------------------------------------------------
__global__ void mask_detect_kernel(const unsigned* __restrict__ w)
{
    __shared__ unsigned sflags;
    if (threadIdx.x == 0) sflags = 0u;
    __syncthreads();

    unsigned f = 0u;
    for (int idx = threadIdx.x; idx < 65536; idx += blockDim.x) {
        const unsigned x = w[idx];
        if (x == 0x3F800000u)                      f |= 4u;   // float 1.0f
        else if ((x & 0xFFFFFF00u) != 0u)          f |= 1u;   // u8 pattern
    }
    if (f) atomicOr(&sflags, f);
    __syncthreads();
    if (threadIdx.x == 0) {
        const unsigned fl = sflags;
        g_mask_kind = (fl & 4u) ? 2u : ((fl & 1u) ? 0u : 1u);
    }
}

// Normalize mask to u8 {0,1} regardless of stored dtype.
__global__ void mask_convert_kernel(const void* __restrict__ src)
{
    const unsigned kind = g_mask_kind;
    const int idx = blockIdx.x * blockDim.x + threadIdx.x;   // per 4 elements
    if (idx >= MASK_ELEMS / 4) return;
    uchar4 o;
    if (kind == 0u) {
        const uchar4 v = ((const uchar4*)src)[idx];
        o = make_uchar4(v.x != 0, v.y != 0, v.z != 0, v.w != 0);
    } else if (kind == 1u) {
        const int4 v = ((const int4*)src)[idx];
        o = make_uchar4(v.x != 0, v.y != 0, v.z != 0, v.w != 0);
    } else {
        const float4 v = ((const float4*)src)[idx];
        o = make_uchar4(v.x != 0.0f, v.y != 0.0f, v.z != 0.0f, v.w != 0.0f);
    }
    g_mask4[idx] = o;
}

// ---------------------------------------------------------------------------
// Shared GEMM core.
//   C[64,64] tile of  C = A * op(B)  (+ akbias broadcast along K on A load,
//                                     + cbias broadcast along N on store)
//   B_IS_NK = true :  B is [N,K] row-major (NT gemm, dot of rows)
//   B_IS_NK = false:  B is [K,N] row-major (NN gemm)
// ---------------------------------------------------------------------------
template <bool B_IS_NK>
__device__ __forceinline__ void gemm_core(
    const float* __restrict__ A, int lda,
    const float* __restrict__ B, int ldb,
    float* __restrict__ C, int ldc, int K,
    const float* __restrict__ akbias,
    const float* __restrict__ cbias)
{
    __shared__ float As[BK][BM + 1];
    __shared__ float Bs[BK][BN + 1];

    const int tid = threadIdx.x;          // 0..255
    const int tx  = tid & 15;             // col group
    const int ty  = tid >> 4;             // row group
    const int lm  = tid >> 2;             // 0..63  (row for NT-style loads)
    const int lk  = (tid & 3) << 2;       // 0,4,8,12

    const float* Arow = A + (size_t)lm * lda + lk;

    float acc[4][4] = {};

    for (int kk = 0; kk < K; kk += BK) {
        // ---- load A tile (rows, K-contiguous), add optional K-bias ----
        float4 a4 = *(const float4*)(Arow + kk);
        if (akbias) {
            const float* ub = akbias + kk + lk;
            a4.x += ub[0]; a4.y += ub[1]; a4.z += ub[2]; a4.w += ub[3];
        }
        As[lk + 0][lm] = a4.x;
        As[lk + 1][lm] = a4.y;
        As[lk + 2][lm] = a4.z;
        As[lk + 3][lm] = a4.w;

        // ---- load B tile ----
        if (B_IS_NK) {
            const float4 b4 = *(const float4*)(B + (size_t)lm * ldb + kk + lk);
            Bs[lk + 0][lm] = b4.x;
            Bs[lk + 1][lm] = b4.y;
            Bs[lk + 2][lm] = b4.z;
            Bs[lk + 3][lm] = b4.w;
        } else {
            const int bk = tid >> 4;          // 0..15
            const int bn = (tid & 15) << 2;   // 0..60
            const float4 b4 = *(const float4*)(B + (size_t)(kk + bk) * ldb + bn);
            Bs[bk][bn + 0] = b4.x;
            Bs[bk][bn + 1] = b4.y;
            Bs[bk][bn + 2] = b4.z;
            Bs[bk][bn + 3] = b4.w;
        }
        __syncthreads();

        // ---- compute ----
        #pragma unroll
        for (int k = 0; k < BK; ++k) {
            float ar[4], br[4];
            #pragma unroll
            for (int i = 0; i < 4; ++i) ar[i] = As[k][(ty << 2) + i];
            #pragma unroll
            for (int j = 0; j < 4; ++j) br[j] = Bs[k][(tx << 2) + j];
            #pragma unroll
            for (int i = 0; i < 4; ++i)
                #pragma unroll
                for (int j = 0; j < 4; ++j)
                    acc[i][j] += ar[i] * br[j];
        }
        __syncthreads();
    }

    // ---- store ----
    #pragma unroll
    for (int i = 0; i < 4; ++i) {
        float* Crow = C + (size_t)((ty << 2) + i) * ldc + (tx << 2);
        #pragma unroll
        for (int j = 0; j < 4; ++j) {
            float v = acc[i][j];
            if (cbias) v += cbias[(tx << 2) + j];
            Crow[j] = v;
        }
    }
}

// ---------------------------------------------------------------------------
// 1) Fused input projections: z selects {Q, K, V, P}
// ---------------------------------------------------------------------------
__global__ __launch_bounds__(256)
void proj_kernel(const float* __restrict__ q, const float* __restrict__ k,
                 const float* __restrict__ v, const float* __restrict__ pe,
                 const float* __restrict__ Wq, const float* __restrict__ bq,
                 const float* __restrict__ Wk, const float* __restrict__ bk,
                 const float* __restrict__ Wv, const float* __restrict__ bv,
                 const float* __restrict__ Wpos)
{
    const float* X;  const float* W;  const float* bias;  float* out;
    switch (blockIdx.z) {
        case 0:  X = q;  W = Wq;   bias = bq;      out = g_Q;  break;
        case 1:  X = k;  W = Wk;   bias = bk;      out = g_Kp; break;
        case 2:  X = v;  W = Wv;   bias = bv;      out = g_Vp; break;
        default: X = pe; W = Wpos; bias = nullptr; out = g_Pp; break;
    }
    const float* A  = X + (size_t)blockIdx.y * BM * D;
    const float* B  = W + (size_t)blockIdx.x * BN * D;
    float*       C  = out + (size_t)blockIdx.y * BM * D + blockIdx.x * BN;
    const float* cb = bias ? bias + blockIdx.x * BN : nullptr;
    gemm_core<true>(A, D, B, D, C, D, D, nullptr, cb);
}

// ---------------------------------------------------------------------------
// 2) Score GEMMs (batched over b*h), NT with K=64
// ---------------------------------------------------------------------------
__global__ __launch_bounds__(256)
void score_kernel(const float* __restrict__ u, const float* __restrict__ vb,
                  float* __restrict__ attn_out, int which)
{
    const int bh = blockIdx.z;
    const int b  = bh >> 3;
    const int h  = bh & 7;
    const size_t head_off = (size_t)b * S * D + (size_t)h * HD;

    const float* A  = g_Q + head_off + (size_t)blockIdx.y * BM * D;
    const float* B  = (which ? g_Pp : g_Kp) + head_off + (size_t)blockIdx.x * BN * D;
    float*       C  = (which ? g_pos : attn_out)
                      + (size_t)bh * S * S + (size_t)blockIdx.y * BM * S + blockIdx.x * BN;
    const float* kb = (which ? vb : u) + h * HD;
    gemm_core<true>(A, D, B, D, C, S, HD, kb, nullptr);
}

// ---------------------------------------------------------------------------
// 3) Fused relative-shift + scale + mask + softmax, in place on attn region.
//    shifted[i,j] = pos_raw[i, S-1-i+j]        (j <= i)
//                 = 0                          (j == i+1)
//                 = pos_raw[i+1, j-i-2]        (j >  i+1)
// ---------------------------------------------------------------------------
__global__ __launch_bounds__(256)
void softmax_kernel(float* __restrict__ attn)
{
    const int r  = blockIdx.x;        // 0 .. B*H*S-1
    const int i  = r & (S - 1);       // query index
    const int bh = r >> 10;
    const int b  = bh >> 3;

    float* row               = attn + (size_t)r * S;
    const float* prow        = g_pos + (size_t)r * S;  // pos_raw row i (row i+1 = prow+S)
    const unsigned char* mrw = (const unsigned char*)g_mask4 + ((size_t)b * S + i) * S;

    const float scale = 0.04419417382415922f;   // 1/sqrt(512)
    const int tid = threadIdx.x;

    float vals[4];
    float mx = -3.4e38f;
    #pragma unroll
    for (int t = 0; t < 4; ++t) {
        const int j = tid + (t << 8);
        const float c = row[j];
        float p;
        if (j <= i)          p = prow[S - 1 - i + j];
        else if (j == i + 1) p = 0.0f;
        else                 p = prow[S + j - i - 2];
        float sc = (c + p) * scale;
        if (mrw[j]) sc = -10000.0f;
        vals[t] = sc;
        mx = fmaxf(mx, sc);
    }

    __shared__ float sred[8];
    __shared__ float ssum[8];

    #pragma unroll
    for (int o = 16; o; o >>= 1) mx = fmaxf(mx, __shfl_xor_sync(0xffffffffu, mx, o));
    if ((tid & 31) == 0) sred[tid >> 5] = mx;
    __syncthreads();
    if (tid < 32) {
        float v = (tid < 8) ? sred[tid] : -3.4e38f;
        #pragma unroll
        for (int o = 4; o; o >>= 1) v = fmaxf(v, __shfl_xor_sync(0xffffffffu, v, o));
        if (tid == 0) sred[0] = v;
    }
    __syncthreads();
    const float rowmax = sred[0];

    float s = 0.0f;
    #pragma unroll
    for (int t = 0; t < 4; ++t) { vals[t] = __expf(vals[t] - rowmax); s += vals[t]; }

    #pragma unroll
    for (int o = 16; o; o >>= 1) s += __shfl_xor_sync(0xffffffffu, s, o);
    if ((tid & 31) == 0) ssum[tid >> 5] = s;
    __syncthreads();
    if (tid < 32) {
        float v = (tid < 8) ? ssum[tid] : 0.0f;
        #pragma unroll
        for (int o = 4; o; o >>= 1) v += __shfl_xor_sync(0xffffffffu, v, o);
        if (tid == 0) ssum[0] = v;
    }
    __syncthreads();
    const float inv = 1.0f / ssum[0];

    #pragma unroll
    for (int t = 0; t < 4; ++t) row[tid + (t << 8)] = vals[t] * inv;
}

// ---------------------------------------------------------------------------
// 4) context = attn @ V (batched over b*h), NN with N=64, K=1024
// ---------------------------------------------------------------------------
__global__ __launch_bounds__(256)
void av_kernel(const float* __restrict__ attn)
{
    const int bh = blockIdx.z;
    const int b  = bh >> 3;
    const int h  = bh & 7;

    const float* A = attn + (size_t)bh * S * S + (size_t)blockIdx.y * BM * S;
    const float* B = g_Vp + (size_t)b * S * D + (size_t)h * HD;   // [K=S rows, ldb=D]
    float*       C = g_ctx + (size_t)b * S * D + (size_t)h * HD
                     + (size_t)blockIdx.y * BM * D;
    gemm_core<false>(A, S, B, D, C, D, S, nullptr, nullptr);
}

// ---------------------------------------------------------------------------
// 5) out = ctx @ Wout^T + bout
// ---------------------------------------------------------------------------
__global__ __launch_bounds__(256)
void outproj_kernel(const float* __restrict__ Wout, const float* __restrict__ bout,
                    float* __restrict__ out)
{
    const float* A = g_ctx + (size_t)blockIdx.y * BM * D;
    const float* B = Wout + (size_t)blockIdx.x * BN * D;
    float*       C = out + (size_t)blockIdx.y * BM * D + blockIdx.x * BN;
    gemm_core<true>(A, D, B, D, C, D, D, nullptr, bout + blockIdx.x * BN);
}

// ---------------------------------------------------------------------------
// Launch
// ---------------------------------------------------------------------------
extern "C" void kernel_launch(void* const* d_in, const int* in_sizes, int n_in,
                              void* d_out, int out_size)
{
    const float* q    = (const float*)d_in[0];
    const float* k    = (const float*)d_in[1];
    const float* v    = (const float*)d_in[2];
    const float* pe   = (const float*)d_in[3];
    const void*  mask = d_in[4];
    const float* Wq   = (const float*)d_in[5];
    const float* bq   = (const float*)d_in[6];
    const float* Wk   = (const float*)d_in[7];
    const float* bk   = (const float*)d_in[8];
    const float* Wv   = (const float*)d_in[9];
    const float* bv   = (const float*)d_in[10];
    const float* Wpos = (const float*)d_in[11];
    const float* Wout = (const float*)d_in[12];
    const float* bout = (const float*)d_in[13];
    const float* u    = (const float*)d_in[14];
    const float* vb   = (const float*)d_in[15];

    float* out_ctx  = (float*)d_out;                         // [8,1024,512]
    float* out_attn = out_ctx + (size_t)BS * D;              // [8,8,1024,1024]

    const dim3 blk(256);

    // 0) normalize mask to u8 regardless of stored dtype
    mask_detect_kernel<<<1, 1024>>>((const unsigned*)mask);
    mask_convert_kernel<<<(MASK_ELEMS / 4 + 255) / 256, 256>>>(mask);

    // 1) projections (Q,K,V,P)
    proj_kernel<<<dim3(D / BN, BS / BM, 4), blk>>>(q, k, v, pe,
                                                   Wq, bq, Wk, bk, Wv, bv, Wpos);
    // 2) content scores -> attn region ; raw pos scores -> g_pos
    score_kernel<<<dim3(S / BN, S / BM, BATCH * NH), blk>>>(u, vb, out_attn, 0);
    score_kernel<<<dim3(S / BN, S / BM, BATCH * NH), blk>>>(u, vb, out_attn, 1);
    // 3) shift + scale + mask + softmax (in place)
    softmax_kernel<<<BATCH * NH * S, blk>>>(out_attn);
    // 4) context = attn @ V
    av_kernel<<<dim3(1, S / BM, BATCH * NH), blk>>>(out_attn);
    // 5) output projection
    outproj_kernel<<<dim3(D / BN, BS / BM, 1), blk>>>(Wout, bout, out_ctx);
}

// round 4
// speedup vs baseline: 2.3310x; 2.3310x over previous
#include <cuda_runtime.h>
#include <cstdint>
#include <cstddef>

// Problem constants
#define S     1024
#define D     512
#define NH    8
#define HD    64
#define BATCH 8
#define BS    (BATCH * S)      // 8192 rows

#define MASK_ELEMS (BATCH * S * S)   // 8,388,608

// MMA tiling: block 128 x BN_, 8 warps (4 along M, 2 along N), warp tile 32 x (NI*8)
#define BM  128
#define BK  16
#define ASTRIDE 20               // 16 k-words + 4 pad (conflict-free frag loads)

// ---------------------------------------------------------------------------
// Scratch (static device globals -- no allocations allowed in kernel_launch)
// ---------------------------------------------------------------------------
__device__ float g_Q[BS * D];
__device__ float g_Kp[BS * D];
__device__ float g_Vp[BS * D];
__device__ float g_Pp[BS * D];
__device__ float g_ctx[BS * D];
__device__ float g_pos[67108864];            // raw pos scores [B,H,S,S]
__device__ uchar4 g_mask4[MASK_ELEMS / 4];   // normalized mask (u8 0/1)
__device__ unsigned g_mask_kind;             // 0 = u8/bool, 1 = int32, 2 = float32

// ---------------------------------------------------------------------------
// Mask dtype detection + normalization (unchanged from R3 -- proven correct)
// ---------------------------------------------------------------------------
__global__ void mask_detect_kernel(const unsigned* __restrict__ w)
{
    __shared__ unsigned sflags;
    if (threadIdx.x == 0) sflags = 0u;
    __syncthreads();
    unsigned f = 0u;
    for (int idx = threadIdx.x; idx < 65536; idx += blockDim.x) {
        const unsigned x = w[idx];
        if (x == 0x3F800000u)             f |= 4u;
        else if ((x & 0xFFFFFF00u) != 0u) f |= 1u;
    }
    if (f) atomicOr(&sflags, f);
    __syncthreads();
    if (threadIdx.x == 0) {
        const unsigned fl = sflags;
        g_mask_kind = (fl & 4u) ? 2u : ((fl & 1u) ? 0u : 1u);
    }
}

__global__ void mask_convert_kernel(const void* __restrict__ src)
{
    const unsigned kind = g_mask_kind;
    const int idx = blockIdx.x * blockDim.x + threadIdx.x;
    if (idx >= MASK_ELEMS / 4) return;
    uchar4 o;
    if (kind == 0u) {
        const uchar4 v = ((const uchar4*)src)[idx];
        o = make_uchar4(v.x != 0, v.y != 0, v.z != 0, v.w != 0);
    } else if (kind == 1u) {
        const int4 v = ((const int4*)src)[idx];
        o = make_uchar4(v.x != 0, v.y != 0, v.z != 0, v.w != 0);
    } else {
        const float4 v = ((const float4*)src)[idx];
        o = make_uchar4(v.x != 0.0f, v.y != 0.0f, v.z != 0.0f, v.w != 0.0f);
    }
    g_mask4[idx] = o;
}

// ---------------------------------------------------------------------------
// tf32 helpers
// ---------------------------------------------------------------------------
__device__ __forceinline__ unsigned f2tf32(float x)
{
    unsigned r;
    asm("cvt.rna.tf32.f32 %0, %1;" : "=r"(r) : "f"(x));
    return r;
}

__device__ __forceinline__ void mma_tf32(float* d, const unsigned* a, const unsigned* b)
{
    asm volatile(
        "mma.sync.aligned.m16n8k8.row.col.f32.tf32.tf32.f32 "
        "{%0,%1,%2,%3}, {%4,%5,%6,%7}, {%8,%9}, {%0,%1,%2,%3};\n"
        : "+f"(d[0]), "+f"(d[1]), "+f"(d[2]), "+f"(d[3])
        : "r"(a[0]), "r"(a[1]), "r"(a[2]), "r"(a[3]), "r"(b[0]), "r"(b[1]));
}

// ---------------------------------------------------------------------------
// Tensor-core GEMM core (tf32, fp32 accumulate).
//   C[BM, BN_] tile of C = A * op(B)
//   B_IS_NK = true : B is [N,K] row-major (NT)
//   B_IS_NK = false: B is [K,N] row-major (NN)
//   akbias: optional bias added to A along K before tf32 convert
//   cbias : optional bias added to C along N at store
//   K % 16 == 0 required.
// ---------------------------------------------------------------------------
template <int BN_, int NI, bool B_IS_NK>
__device__ __forceinline__ void gemm_mma(
    const float* __restrict__ A, int lda,
    const float* __restrict__ B, int ldb,
    float* __restrict__ C, int ldc, int K,
    const float* __restrict__ akbias,
    const float* __restrict__ cbias)
{
    constexpr int WTN = NI * 8;                    // warp tile N
    constexpr int BROWSTRIDE = BN_ + 8;            // NN layout row stride (words)
    constexpr int BSZ = B_IS_NK ? (BN_ * ASTRIDE) : (BK * BROWSTRIDE);

    __shared__ unsigned As[BM * ASTRIDE];
    __shared__ unsigned Bs[BSZ];

    const int tid  = threadIdx.x;                  // 0..255
    const int lane = tid & 31;
    const int warp = tid >> 5;                     // 0..7
    const int g    = lane >> 2;                    // 0..7
    const int tig  = lane & 3;                     // 0..3
    const int wm   = (warp >> 1) * 32;             // warp M offset: 0,32,64,96
    const int wn   = (warp & 1) * WTN;             // warp N offset

    float acc[2][NI][4];
    #pragma unroll
    for (int mi = 0; mi < 2; ++mi)
        #pragma unroll
        for (int ni = 0; ni < NI; ++ni)
            #pragma unroll
            for (int r = 0; r < 4; ++r) acc[mi][ni][r] = 0.0f;

    for (int kk = 0; kk < K; kk += BK) {
        // ---- fill As: BM rows x 16 k (float4 per thread, STS.128) ----
        #pragma unroll
        for (int t = 0; t < (BM * 4) / 256; ++t) {
            const int f4  = tid + t * 256;
            const int row = f4 >> 2;
            const int kq  = f4 & 3;
            float4 v = *(const float4*)(A + (size_t)row * lda + kk + kq * 4);
            if (akbias) {
                const float* ub = akbias + kk + kq * 4;
                v.x += ub[0]; v.y += ub[1]; v.z += ub[2]; v.w += ub[3];
            }
            uint4 w;
            w.x = f2tf32(v.x); w.y = f2tf32(v.y);
            w.z = f2tf32(v.z); w.w = f2tf32(v.w);
            *(uint4*)&As[row * ASTRIDE + kq * 4] = w;
        }
        // ---- fill Bs ----
        if (B_IS_NK) {
            #pragma unroll
            for (int t = 0; t < (BN_ * 4) / 256; ++t) {
                const int f4  = tid + t * 256;
                const int row = f4 >> 2;          // n index
                const int kq  = f4 & 3;
                const float4 v = *(const float4*)(B + (size_t)row * ldb + kk + kq * 4);
                uint4 w;
                w.x = f2tf32(v.x); w.y = f2tf32(v.y);
                w.z = f2tf32(v.z); w.w = f2tf32(v.w);
                *(uint4*)&Bs[row * ASTRIDE + kq * 4] = w;
            }
        } else {
            // B[K,N]: rows k, n-contiguous -> Bs[k][n]
            constexpr int F4_PER_ROW = BN_ / 4;
            #pragma unroll
            for (int t = 0; t < (BK * F4_PER_ROW) / 256; ++t) {
                const int f4 = tid + t * 256;
                const int k  = f4 / F4_PER_ROW;
                const int nq = f4 % F4_PER_ROW;
                const float4 v = *(const float4*)(B + (size_t)(kk + k) * ldb + nq * 4);
                uint4 w;
                w.x = f2tf32(v.x); w.y = f2tf32(v.y);
                w.z = f2tf32(v.z); w.w = f2tf32(v.w);
                *(uint4*)&Bs[k * BROWSTRIDE + nq * 4] = w;
            }
        }
        __syncthreads();

        // ---- compute: 2 k-slices of 8 ----
        #pragma unroll
        for (int ks = 0; ks < BK; ks += 8) {
            unsigned af[2][4];
            #pragma unroll
            for (int mi = 0; mi < 2; ++mi) {
                const unsigned* ap = &As[(wm + mi * 16 + g) * ASTRIDE + ks + tig];
                af[mi][0] = ap[0];
                af[mi][1] = ap[8 * ASTRIDE];
                af[mi][2] = ap[4];
                af[mi][3] = ap[8 * ASTRIDE + 4];
            }
            unsigned bf[NI][2];
            #pragma unroll
            for (int ni = 0; ni < NI; ++ni) {
                if (B_IS_NK) {
                    const unsigned* bp = &Bs[(wn + ni * 8 + g) * ASTRIDE + ks + tig];
                    bf[ni][0] = bp[0];
                    bf[ni][1] = bp[4];
                } else {
                    const unsigned* bp = &Bs[(ks + tig) * BROWSTRIDE + wn + ni * 8 + g];
                    bf[ni][0] = bp[0];
                    bf[ni][1] = bp[4 * BROWSTRIDE];
                }
            }
            #pragma unroll
            for (int mi = 0; mi < 2; ++mi)
                #pragma unroll
                for (int ni = 0; ni < NI; ++ni)
                    mma_tf32(acc[mi][ni], af[mi], bf[ni]);
        }
        __syncthreads();
    }

    // ---- store ----
    #pragma unroll
    for (int mi = 0; mi < 2; ++mi) {
        #pragma unroll
        for (int ni = 0; ni < NI; ++ni) {
            const int r0 = wm + mi * 16 + g;
            const int c  = wn + ni * 8 + tig * 2;
            float b0 = 0.0f, b1 = 0.0f;
            if (cbias) { b0 = cbias[c]; b1 = cbias[c + 1]; }
            float* p0 = C + (size_t)r0 * ldc + c;
            float* p1 = p0 + 8 * (size_t)ldc;
            p0[0] = acc[mi][ni][0] + b0;
            p0[1] = acc[mi][ni][1] + b1;
            p1[0] = acc[mi][ni][2] + b0;
            p1[1] = acc[mi][ni][3] + b1;
        }
    }
}

// ---------------------------------------------------------------------------
// 1) Fused input projections: z selects {Q, K, V, P}; NT, K=512
// ---------------------------------------------------------------------------
__global__ __launch_bounds__(256, 2)
void proj_kernel(const float* __restrict__ q, const float* __restrict__ k,
                 const float* __restrict__ v, const float* __restrict__ pe,
                 const float* __restrict__ Wq, const float* __restrict__ bq,
                 const float* __restrict__ Wk, const float* __restrict__ bk,
                 const float* __restrict__ Wv, const float* __restrict__ bv,
                 const float* __restrict__ Wpos)
{
    const float* X;  const float* W;  const float* bias;  float* out;
    switch (blockIdx.z) {
        case 0:  X = q;  W = Wq;   bias = bq;      out = g_Q;  break;
        case 1:  X = k;  W = Wk;   bias = bk;      out = g_Kp; break;
        case 2:  X = v;  W = Wv;   bias = bv;      out = g_Vp; break;
        default: X = pe; W = Wpos; bias = nullptr; out = g_Pp; break;
    }
    const float* A  = X + (size_t)blockIdx.y * BM * D;
    const float* B  = W + (size_t)blockIdx.x * 128 * D;
    float*       C  = out + (size_t)blockIdx.y * BM * D + blockIdx.x * 128;
    const float* cb = bias ? bias + blockIdx.x * 128 : nullptr;
    gemm_mma<128, 8, true>(A, D, B, D, C, D, D, nullptr, cb);
}

// ---------------------------------------------------------------------------
// 2) Score GEMMs (batched over b*h), NT, K=64
// ---------------------------------------------------------------------------
__global__ __launch_bounds__(256, 2)
void score_kernel(const float* __restrict__ u, const float* __restrict__ vb,
                  float* __restrict__ attn_out, int which)
{
    const int bh = blockIdx.z;
    const int b  = bh >> 3;
    const int h  = bh & 7;
    const size_t head_off = (size_t)b * S * D + (size_t)h * HD;

    const float* A  = g_Q + head_off + (size_t)blockIdx.y * BM * D;
    const float* B  = (which ? g_Pp : g_Kp) + head_off + (size_t)blockIdx.x * 128 * D;
    float*       C  = (which ? g_pos : attn_out)
                      + (size_t)bh * S * S + (size_t)blockIdx.y * BM * S + blockIdx.x * 128;
    const float* kb = (which ? vb : u) + h * HD;
    gemm_mma<128, 8, true>(A, D, B, D, C, S, HD, kb, nullptr);
}

// ---------------------------------------------------------------------------
// 3) Fused relative-shift + scale + mask + softmax (unchanged, proven)
// ---------------------------------------------------------------------------
__global__ __launch_bounds__(256)
void softmax_kernel(float* __restrict__ attn)
{
    const int r  = blockIdx.x;
    const int i  = r & (S - 1);
    const int bh = r >> 10;
    const int b  = bh >> 3;

    float* row               = attn + (size_t)r * S;
    const float* prow        = g_pos + (size_t)r * S;
    const unsigned char* mrw = (const unsigned char*)g_mask4 + ((size_t)b * S + i) * S;

    const float scale = 0.04419417382415922f;   // 1/sqrt(512)
    const int tid = threadIdx.x;

    float vals[4];
    float mx = -3.4e38f;
    #pragma unroll
    for (int t = 0; t < 4; ++t) {
        const int j = tid + (t << 8);
        const float c = row[j];
        float p;
        if (j <= i)          p = prow[S - 1 - i + j];
        else if (j == i + 1) p = 0.0f;
        else                 p = prow[S + j - i - 2];
        float sc = (c + p) * scale;
        if (mrw[j]) sc = -10000.0f;
        vals[t] = sc;
        mx = fmaxf(mx, sc);
    }

    __shared__ float sred[8];
    __shared__ float ssum[8];

    #pragma unroll
    for (int o = 16; o; o >>= 1) mx = fmaxf(mx, __shfl_xor_sync(0xffffffffu, mx, o));
    if ((tid & 31) == 0) sred[tid >> 5] = mx;
    __syncthreads();
    if (tid < 32) {
        float v = (tid < 8) ? sred[tid] : -3.4e38f;
        #pragma unroll
        for (int o = 4; o; o >>= 1) v = fmaxf(v, __shfl_xor_sync(0xffffffffu, v, o));
        if (tid == 0) sred[0] = v;
    }
    __syncthreads();
    const float rowmax = sred[0];

    float s = 0.0f;
    #pragma unroll
    for (int t = 0; t < 4; ++t) { vals[t] = __expf(vals[t] - rowmax); s += vals[t]; }

    #pragma unroll
    for (int o = 16; o; o >>= 1) s += __shfl_xor_sync(0xffffffffu, s, o);
    if ((tid & 31) == 0) ssum[tid >> 5] = s;
    __syncthreads();
    if (tid < 32) {
        float v = (tid < 8) ? ssum[tid] : 0.0f;
        #pragma unroll
        for (int o = 4; o; o >>= 1) v += __shfl_xor_sync(0xffffffffu, v, o);
        if (tid == 0) ssum[0] = v;
    }
    __syncthreads();
    const float inv = 1.0f / ssum[0];

    #pragma unroll
    for (int t = 0; t < 4; ++t) row[tid + (t << 8)] = vals[t] * inv;
}

// ---------------------------------------------------------------------------
// 4) context = attn @ V (batched over b*h), NN, K=1024, N=64
// ---------------------------------------------------------------------------
__global__ __launch_bounds__(256, 2)
void av_kernel(const float* __restrict__ attn)
{
    const int bh = blockIdx.z;
    const int b  = bh >> 3;
    const int h  = bh & 7;

    const float* A = attn + (size_t)bh * S * S + (size_t)blockIdx.y * BM * S;
    const float* B = g_Vp + (size_t)b * S * D + (size_t)h * HD;   // [K=S rows, ldb=D]
    float*       C = g_ctx + (size_t)b * S * D + (size_t)h * HD
                     + (size_t)blockIdx.y * BM * D;
    gemm_mma<64, 4, false>(A, S, B, D, C, D, S, nullptr, nullptr);
}

// ---------------------------------------------------------------------------
// 5) out = ctx @ Wout^T + bout ; NT, K=512
// ---------------------------------------------------------------------------
__global__ __launch_bounds__(256, 2)
void outproj_kernel(const float* __restrict__ Wout, const float* __restrict__ bout,
                    float* __restrict__ out)
{
    const float* A = g_ctx + (size_t)blockIdx.y * BM * D;
    const float* B = Wout + (size_t)blockIdx.x * 128 * D;
    float*       C = out + (size_t)blockIdx.y * BM * D + blockIdx.x * 128;
    gemm_mma<128, 8, true>(A, D, B, D, C, D, D, nullptr, bout + blockIdx.x * 128);
}

// ---------------------------------------------------------------------------
// Launch
// ---------------------------------------------------------------------------
extern "C" void kernel_launch(void* const* d_in, const int* in_sizes, int n_in,
                              void* d_out, int out_size)
{
    const float* q    = (const float*)d_in[0];
    const float* k    = (const float*)d_in[1];
    const float* v    = (const float*)d_in[2];
    const float* pe   = (const float*)d_in[3];
    const void*  mask = d_in[4];
    const float* Wq   = (const float*)d_in[5];
    const float* bq   = (const float*)d_in[6];
    const float* Wk   = (const float*)d_in[7];
    const float* bk   = (const float*)d_in[8];
    const float* Wv   = (const float*)d_in[9];
    const float* bv   = (const float*)d_in[10];
    const float* Wpos = (const float*)d_in[11];
    const float* Wout = (const float*)d_in[12];
    const float* bout = (const float*)d_in[13];
    const float* u    = (const float*)d_in[14];
    const float* vb   = (const float*)d_in[15];

    float* out_ctx  = (float*)d_out;                 // [8,1024,512]
    float* out_attn = out_ctx + (size_t)BS * D;      // [8,8,1024,1024]

    const dim3 blk(256);

    // 0) normalize mask
    mask_detect_kernel<<<1, 1024>>>((const unsigned*)mask);
    mask_convert_kernel<<<(MASK_ELEMS / 4 + 255) / 256, 256>>>(mask);

    // 1) projections (Q,K,V,P)
    proj_kernel<<<dim3(D / 128, BS / BM, 4), blk>>>(q, k, v, pe,
                                                    Wq, bq, Wk, bk, Wv, bv, Wpos);
    // 2) content scores -> attn region ; raw pos scores -> g_pos
    score_kernel<<<dim3(S / 128, S / BM, BATCH * NH), blk>>>(u, vb, out_attn, 0);
    score_kernel<<<dim3(S / 128, S / BM, BATCH * NH), blk>>>(u, vb, out_attn, 1);
    // 3) shift + scale + mask + softmax (in place)
    softmax_kernel<<<BATCH * NH * S, blk>>>(out_attn);
    // 4) context = attn @ V
    av_kernel<<<dim3(1, S / BM, BATCH * NH), blk>>>(out_attn);
    // 5) output projection
    outproj_kernel<<<dim3(D / 128, BS / BM, 1), blk>>>(Wout, bout, out_ctx);
}

// round 5
// speedup vs baseline: 2.8183x; 1.2091x over previous
#include <cuda_runtime.h>
#include <cstdint>
#include <cstddef>

// Problem constants
#define S     1024
#define D     512
#define NH    8
#define HD    64
#define BATCH 8
#define BS    (BATCH * S)      // 8192 rows

#define MASK_ELEMS (BATCH * S * S)   // 8,388,608

// MMA tiling: block 128 x BN_, 8 warps (4 along M, 2 along N)
#define BM  128
#define BK  16
#define ASTR 20                // 16 k-words + 4 pad (conflict-free frag loads)

// ---------------------------------------------------------------------------
// Scratch (static device globals -- no allocations allowed in kernel_launch)
// ---------------------------------------------------------------------------
__device__ float g_Qu[BS * D];               // q proj + bq + u   (per-column)
__device__ float g_Qv[BS * D];               // q proj + bq + v_bias
__device__ float g_Kp[BS * D];
__device__ float g_Vp[BS * D];
__device__ float g_Pp[BS * D];
__device__ float g_ctx[BS * D];
__device__ float g_pos[67108864];            // raw pos scores [B,H,S,S]
__device__ uchar4 g_mask4[MASK_ELEMS / 4];   // normalized mask (u8 0/1)
__device__ unsigned g_mask_kind;

// ---------------------------------------------------------------------------
// Mask dtype detection + normalization (proven correct)
// ---------------------------------------------------------------------------
__global__ void mask_detect_kernel(const unsigned* __restrict__ w)
{
    __shared__ unsigned sflags;
    if (threadIdx.x == 0) sflags = 0u;
    __syncthreads();
    unsigned f = 0u;
    for (int idx = threadIdx.x; idx < 65536; idx += blockDim.x) {
        const unsigned x = w[idx];
        if (x == 0x3F800000u)             f |= 4u;
        else if ((x & 0xFFFFFF00u) != 0u) f |= 1u;
    }
    if (f) atomicOr(&sflags, f);
    __syncthreads();
    if (threadIdx.x == 0) {
        const unsigned fl = sflags;
        g_mask_kind = (fl & 4u) ? 2u : ((fl & 1u) ? 0u : 1u);
    }
}

__global__ void mask_convert_kernel(const void* __restrict__ src)
{
    const unsigned kind = g_mask_kind;
    const int idx = blockIdx.x * blockDim.x + threadIdx.x;
    if (idx >= MASK_ELEMS / 4) return;
    uchar4 o;
    if (kind == 0u) {
        const uchar4 v = ((const uchar4*)src)[idx];
        o = make_uchar4(v.x != 0, v.y != 0, v.z != 0, v.w != 0);
    } else if (kind == 1u) {
        const int4 v = ((const int4*)src)[idx];
        o = make_uchar4(v.x != 0, v.y != 0, v.z != 0, v.w != 0);
    } else {
        const float4 v = ((const float4*)src)[idx];
        o = make_uchar4(v.x != 0.0f, v.y != 0.0f, v.z != 0.0f, v.w != 0.0f);
    }
    g_mask4[idx] = o;
}

// ---------------------------------------------------------------------------
// Async-copy + tf32 helpers
// ---------------------------------------------------------------------------
__device__ __forceinline__ void cp16(void* smem, const void* gmem)
{
    const unsigned s = (unsigned)__cvta_generic_to_shared(smem);
    asm volatile("cp.async.cg.shared.global [%0], [%1], 16;\n" :: "r"(s), "l"(gmem));
}
__device__ __forceinline__ void cp_commit()
{
    asm volatile("cp.async.commit_group;\n" ::: "memory");
}
__device__ __forceinline__ void cp_wait1()
{
    asm volatile("cp.async.wait_group 1;\n" ::: "memory");
}

__device__ __forceinline__ unsigned f2tf32(float x)
{
    unsigned r;
    asm("cvt.rna.tf32.f32 %0, %1;" : "=r"(r) : "f"(x));
    return r;
}

__device__ __forceinline__ void mma_tf32(float* d, const unsigned* a, const unsigned* b)
{
    asm volatile(
        "mma.sync.aligned.m16n8k8.row.col.f32.tf32.tf32.f32 "
        "{%0,%1,%2,%3}, {%4,%5,%6,%7}, {%8,%9}, {%0,%1,%2,%3};\n"
        : "+f"(d[0]), "+f"(d[1]), "+f"(d[2]), "+f"(d[3])
        : "r"(a[0]), "r"(a[1]), "r"(a[2]), "r"(a[3]), "r"(b[0]), "r"(b[1]));
}

// ---------------------------------------------------------------------------
// Tensor-core GEMM core: tf32, fp32 accumulate, 2-stage cp.async pipeline.
//   C[BM, BN_] tile of C = A * op(B)  (+ cbias along N at store)
//   B_IS_NK = true : B is [N,K] row-major (NT)
//   B_IS_NK = false: B is [K,N] row-major (NN)
//   K % 16 == 0.
// ---------------------------------------------------------------------------
template <int BN_, int NI, bool B_IS_NK>
__device__ __forceinline__ void gemm_mma(
    const float* __restrict__ A, int lda,
    const float* __restrict__ B, int ldb,
    float* __restrict__ C, int ldc, int K,
    const float* __restrict__ cbias)
{
    constexpr int WTN   = NI * 8;
    constexpr int BRS   = BN_ + 8;                 // NN row stride (words)
    constexpr int ATILE = BM * ASTR;
    constexpr int BTILE = B_IS_NK ? (BN_ * ASTR) : (BK * BRS);

    __shared__ float As[2][ATILE];
    __shared__ float Bs[2][BTILE];

    const int tid  = threadIdx.x;
    const int lane = tid & 31;
    const int warp = tid >> 5;
    const int g    = lane >> 2;
    const int tig  = lane & 3;
    const int wm   = (warp >> 1) * 32;
    const int wn   = (warp & 1) * WTN;

    float acc[2][NI][4];
    #pragma unroll
    for (int mi = 0; mi < 2; ++mi)
        #pragma unroll
        for (int ni = 0; ni < NI; ++ni)
            #pragma unroll
            for (int r = 0; r < 4; ++r) acc[mi][ni][r] = 0.0f;

    // ---- tile fill (async) ----
    auto fill = [&](int st, int kk) {
        // A: BM rows x 16 k-words = BM*4 16B chunks
        #pragma unroll
        for (int c = tid; c < BM * 4; c += 256) {
            const int row = c >> 2, q = c & 3;
            cp16(&As[st][row * ASTR + q * 4], A + (size_t)row * lda + kk + q * 4);
        }
        if (B_IS_NK) {
            #pragma unroll
            for (int c = tid; c < BN_ * 4; c += 256) {
                const int row = c >> 2, q = c & 3;
                cp16(&Bs[st][row * ASTR + q * 4], B + (size_t)row * ldb + kk + q * 4);
            }
        } else {
            constexpr int CPR = BN_ / 4;           // chunks per row
            #pragma unroll
            for (int c = tid; c < BK * CPR; c += 256) {
                const int k = c / CPR, nq = c % CPR;
                cp16(&Bs[st][k * BRS + nq * 4], B + (size_t)(kk + k) * ldb + nq * 4);
            }
        }
        cp_commit();
    };

    const int T = K / BK;
    fill(0, 0);

    for (int t = 0; t < T; ++t) {
        if (t + 1 < T) fill((t + 1) & 1, (t + 1) * BK);
        else           cp_commit();                 // empty group keeps wait math uniform
        cp_wait1();
        __syncthreads();

        const float* as = As[t & 1];
        const float* bs = Bs[t & 1];

        #pragma unroll
        for (int ks = 0; ks < BK; ks += 8) {
            unsigned af[2][4];
            #pragma unroll
            for (int mi = 0; mi < 2; ++mi) {
                const float* ap = &as[(wm + mi * 16 + g) * ASTR + ks + tig];
                af[mi][0] = f2tf32(ap[0]);
                af[mi][1] = f2tf32(ap[8 * ASTR]);
                af[mi][2] = f2tf32(ap[4]);
                af[mi][3] = f2tf32(ap[8 * ASTR + 4]);
            }
            unsigned bf[NI][2];
            #pragma unroll
            for (int ni = 0; ni < NI; ++ni) {
                if (B_IS_NK) {
                    const float* bp = &bs[(wn + ni * 8 + g) * ASTR + ks + tig];
                    bf[ni][0] = f2tf32(bp[0]);
                    bf[ni][1] = f2tf32(bp[4]);
                } else {
                    const float* bp = &bs[(ks + tig) * BRS + wn + ni * 8 + g];
                    bf[ni][0] = f2tf32(bp[0]);
                    bf[ni][1] = f2tf32(bp[4 * BRS]);
                }
            }
            #pragma unroll
            for (int mi = 0; mi < 2; ++mi)
                #pragma unroll
                for (int ni = 0; ni < NI; ++ni)
                    mma_tf32(acc[mi][ni], af[mi], bf[ni]);
        }
        __syncthreads();
    }

    // ---- store ----
    #pragma unroll
    for (int mi = 0; mi < 2; ++mi) {
        #pragma unroll
        for (int ni = 0; ni < NI; ++ni) {
            const int r0 = wm + mi * 16 + g;
            const int c  = wn + ni * 8 + tig * 2;
            float b0 = 0.0f, b1 = 0.0f;
            if (cbias) { b0 = cbias[c]; b1 = cbias[c + 1]; }
            float* p0 = C + (size_t)r0 * ldc + c;
            float* p1 = p0 + 8 * (size_t)ldc;
            p0[0] = acc[mi][ni][0] + b0;
            p0[1] = acc[mi][ni][1] + b1;
            p1[0] = acc[mi][ni][2] + b0;
            p1[1] = acc[mi][ni][3] + b1;
        }
    }
}

// ---------------------------------------------------------------------------
// 1) Input projections. z=0: Q (dual output with +u / +v_bias folded),
//    z=1: K, z=2: V, z=3: pos.  NT, K=512.
// ---------------------------------------------------------------------------
__global__ __launch_bounds__(256, 2)
void proj_kernel(const float* __restrict__ q, const float* __restrict__ k,
                 const float* __restrict__ v, const float* __restrict__ pe,
                 const float* __restrict__ Wq, const float* __restrict__ bq,
                 const float* __restrict__ Wk, const float* __restrict__ bk,
                 const float* __restrict__ Wv, const float* __restrict__ bv,
                 const float* __restrict__ Wpos,
                 const float* __restrict__ u, const float* __restrict__ vb)
{
    if (blockIdx.z == 0) {
        // Q path: compute acc + bq, store twice with +u and +vb (u/vb are
        // exactly per-output-column vectors of length D).
        const float* A = q + (size_t)blockIdx.y * BM * D;
        const float* B = Wq + (size_t)blockIdx.x * 128 * D;
        const size_t co = (size_t)blockIdx.y * BM * D + blockIdx.x * 128;

        // inline epilogue via two stores: do gemm into g_Qu with bias bq+u,
        // then derive g_Qv = g_Qu - u + vb in the same kernel? Simpler: run
        // core once accumulating, then dual-store. We re-use the core by
        // storing to g_Qu with (bq+u) folded... cannot fold two biases in one
        // call; so call core with cbias=bq into g_Qu, then fix up both
        // outputs here is extra traffic. Instead: core stores acc+bq+u into
        // g_Qu; a tiny follow-up kernel builds g_Qv. To keep one pass, we
        // store with cbias=bq+u precomputed? No scratch for bias vectors...
        // => simplest correct: store acc+bq into g_Qu, epilogue kernel adds.
        gemm_mma<128, 8, true>(A, D, B, D, g_Qu + co, D, D, bq + blockIdx.x * 128);
    } else if (blockIdx.z == 1) {
        const float* A = k + (size_t)blockIdx.y * BM * D;
        const float* B = Wk + (size_t)blockIdx.x * 128 * D;
        const size_t co = (size_t)blockIdx.y * BM * D + blockIdx.x * 128;
        gemm_mma<128, 8, true>(A, D, B, D, g_Kp + co, D, D, bk + blockIdx.x * 128);
    } else if (blockIdx.z == 2) {
        const float* A = v + (size_t)blockIdx.y * BM * D;
        const float* B = Wv + (size_t)blockIdx.x * 128 * D;
        const size_t co = (size_t)blockIdx.y * BM * D + blockIdx.x * 128;
        gemm_mma<128, 8, true>(A, D, B, D, g_Vp + co, D, D, bv + blockIdx.x * 128);
    } else {
        const float* A = pe + (size_t)blockIdx.y * BM * D;
        const float* B = Wpos + (size_t)blockIdx.x * 128 * D;
        const size_t co = (size_t)blockIdx.y * BM * D + blockIdx.x * 128;
        gemm_mma<128, 8, true>(A, D, B, D, g_Pp + co, D, D, nullptr);
    }
}

// Build g_Qv = g_Qu + (vb - u); g_Qu += u.   (vectorized, trivial cost)
__global__ __launch_bounds__(256)
void qbias_kernel(const float* __restrict__ u, const float* __restrict__ vb)
{
    const int idx = blockIdx.x * blockDim.x + threadIdx.x;     // per float4
    if (idx >= BS * D / 4) return;
    const int col4 = idx & (D / 4 - 1);
    const float4 base = ((const float4*)g_Qu)[idx];
    const float4 u4   = ((const float4*)u)[col4];
    const float4 v4   = ((const float4*)vb)[col4];
    float4 a, bqv;
    a.x = base.x + u4.x;  a.y = base.y + u4.y;
    a.z = base.z + u4.z;  a.w = base.w + u4.w;
    bqv.x = base.x + v4.x; bqv.y = base.y + v4.y;
    bqv.z = base.z + v4.z; bqv.w = base.w + v4.w;
    ((float4*)g_Qu)[idx] = a;
    ((float4*)g_Qv)[idx] = bqv;
}

// ---------------------------------------------------------------------------
// 2) Score GEMMs (batched over b*h), NT, K=64
// ---------------------------------------------------------------------------
__global__ __launch_bounds__(256, 2)
void score_kernel(float* __restrict__ attn_out, int which)
{
    const int bh = blockIdx.z;
    const int b  = bh >> 3;
    const int h  = bh & 7;
    const size_t head_off = (size_t)b * S * D + (size_t)h * HD;

    const float* A = (which ? g_Qv : g_Qu) + head_off + (size_t)blockIdx.y * BM * D;
    const float* B = (which ? g_Pp : g_Kp) + head_off + (size_t)blockIdx.x * 128 * D;
    float*       C = (which ? g_pos : attn_out)
                     + (size_t)bh * S * S + (size_t)blockIdx.y * BM * S + blockIdx.x * 128;
    gemm_mma<128, 8, true>(A, D, B, D, C, S, HD, nullptr);
}

// ---------------------------------------------------------------------------
// 3) Fused relative-shift + scale + mask + softmax (vectorized loads)
// ---------------------------------------------------------------------------
__global__ __launch_bounds__(256)
void softmax_kernel(float* __restrict__ attn)
{
    const int r  = blockIdx.x;
    const int i  = r & (S - 1);
    const int bh = r >> 10;
    const int b  = bh >> 3;

    float* row               = attn + (size_t)r * S;
    const float* prow        = g_pos + (size_t)r * S;
    const unsigned char* mrw = (const unsigned char*)g_mask4 + ((size_t)b * S + i) * S;

    const float scale = 0.04419417382415922f;   // 1/sqrt(512)
    const int tid = threadIdx.x;
    const int j0  = tid << 2;

    const float4 c4  = *(const float4*)(row + j0);
    const uchar4 m4  = *(const uchar4*)(mrw + j0);
    const float cv[4] = {c4.x, c4.y, c4.z, c4.w};
    const unsigned char mv[4] = {m4.x, m4.y, m4.z, m4.w};

    float vals[4];
    float mx = -3.4e38f;
    #pragma unroll
    for (int e = 0; e < 4; ++e) {
        const int j = j0 + e;
        float p;
        if (j <= i)          p = prow[S - 1 - i + j];
        else if (j == i + 1) p = 0.0f;
        else                 p = prow[S + j - i - 2];
        float sc = (cv[e] + p) * scale;
        if (mv[e]) sc = -10000.0f;
        vals[e] = sc;
        mx = fmaxf(mx, sc);
    }

    __shared__ float sred[8];
    __shared__ float ssum[8];

    #pragma unroll
    for (int o = 16; o; o >>= 1) mx = fmaxf(mx, __shfl_xor_sync(0xffffffffu, mx, o));
    if ((tid & 31) == 0) sred[tid >> 5] = mx;
    __syncthreads();
    if (tid < 32) {
        float v = (tid < 8) ? sred[tid] : -3.4e38f;
        #pragma unroll
        for (int o = 4; o; o >>= 1) v = fmaxf(v, __shfl_xor_sync(0xffffffffu, v, o));
        if (tid == 0) sred[0] = v;
    }
    __syncthreads();
    const float rowmax = sred[0];

    float s = 0.0f;
    #pragma unroll
    for (int e = 0; e < 4; ++e) { vals[e] = __expf(vals[e] - rowmax); s += vals[e]; }

    #pragma unroll
    for (int o = 16; o; o >>= 1) s += __shfl_xor_sync(0xffffffffu, s, o);
    if ((tid & 31) == 0) ssum[tid >> 5] = s;
    __syncthreads();
    if (tid < 32) {
        float v = (tid < 8) ? ssum[tid] : 0.0f;
        #pragma unroll
        for (int o = 4; o; o >>= 1) v += __shfl_xor_sync(0xffffffffu, v, o);
        if (tid == 0) ssum[0] = v;
    }
    __syncthreads();
    const float inv = 1.0f / ssum[0];

    float4 o4;
    o4.x = vals[0] * inv; o4.y = vals[1] * inv;
    o4.z = vals[2] * inv; o4.w = vals[3] * inv;
    *(float4*)(row + j0) = o4;
}

// ---------------------------------------------------------------------------
// 4) context = attn @ V (batched over b*h), NN, K=1024, N=64
// ---------------------------------------------------------------------------
__global__ __launch_bounds__(256, 2)
void av_kernel(const float* __restrict__ attn)
{
    const int bh = blockIdx.z;
    const int b  = bh >> 3;
    const int h  = bh & 7;

    const float* A = attn + (size_t)bh * S * S + (size_t)blockIdx.y * BM * S;
    const float* B = g_Vp + (size_t)b * S * D + (size_t)h * HD;
    float*       C = g_ctx + (size_t)b * S * D + (size_t)h * HD
                     + (size_t)blockIdx.y * BM * D;
    gemm_mma<64, 4, false>(A, S, B, D, C, D, S, nullptr);
}

// ---------------------------------------------------------------------------
// 5) out = ctx @ Wout^T + bout ; NT, K=512
// ---------------------------------------------------------------------------
__global__ __launch_bounds__(256, 2)
void outproj_kernel(const float* __restrict__ Wout, const float* __restrict__ bout,
                    float* __restrict__ out)
{
    const float* A = g_ctx + (size_t)blockIdx.y * BM * D;
    const float* B = Wout + (size_t)blockIdx.x * 128 * D;
    float*       C = out + (size_t)blockIdx.y * BM * D + blockIdx.x * 128;
    gemm_mma<128, 8, true>(A, D, B, D, C, D, D, bout + blockIdx.x * 128);
}

// ---------------------------------------------------------------------------
// Launch
// ---------------------------------------------------------------------------
extern "C" void kernel_launch(void* const* d_in, const int* in_sizes, int n_in,
                              void* d_out, int out_size)
{
    const float* q    = (const float*)d_in[0];
    const float* k    = (const float*)d_in[1];
    const float* v    = (const float*)d_in[2];
    const float* pe   = (const float*)d_in[3];
    const void*  mask = d_in[4];
    const float* Wq   = (const float*)d_in[5];
    const float* bq   = (const float*)d_in[6];
    const float* Wk   = (const float*)d_in[7];
    const float* bk   = (const float*)d_in[8];
    const float* Wv   = (const float*)d_in[9];
    const float* bv   = (const float*)d_in[10];
    const float* Wpos = (const float*)d_in[11];
    const float* Wout = (const float*)d_in[12];
    const float* bout = (const float*)d_in[13];
    const float* u    = (const float*)d_in[14];
    const float* vb   = (const float*)d_in[15];

    float* out_ctx  = (float*)d_out;                 // [8,1024,512]
    float* out_attn = out_ctx + (size_t)BS * D;      // [8,8,1024,1024]

    const dim3 blk(256);

    // 0) normalize mask
    mask_detect_kernel<<<1, 1024>>>((const unsigned*)mask);
    mask_convert_kernel<<<(MASK_ELEMS / 4 + 255) / 256, 256>>>(mask);

    // 1) projections (Q,K,V,P), then fold u/v_bias into Q copies
    proj_kernel<<<dim3(D / 128, BS / BM, 4), blk>>>(q, k, v, pe,
                                                    Wq, bq, Wk, bk, Wv, bv, Wpos,
                                                    u, vb);
    qbias_kernel<<<(BS * D / 4 + 255) / 256, 256>>>(u, vb);

    // 2) content scores -> attn region ; raw pos scores -> g_pos
    score_kernel<<<dim3(S / 128, S / BM, BATCH * NH), blk>>>(out_attn, 0);
    score_kernel<<<dim3(S / 128, S / BM, BATCH * NH), blk>>>(out_attn, 1);
    // 3) shift + scale + mask + softmax (in place)
    softmax_kernel<<<BATCH * NH * S, blk>>>(out_attn);
    // 4) context = attn @ V
    av_kernel<<<dim3(1, S / BM, BATCH * NH), blk>>>(out_attn);
    // 5) output projection
    outproj_kernel<<<dim3(D / 128, BS / BM, 1), blk>>>(Wout, bout, out_ctx);
}

// round 7
// speedup vs baseline: 2.9429x; 1.0442x over previous
#include <cuda_runtime.h>
#include <cstdint>
#include <cstddef>

// Problem constants
#define S     1024
#define D     512
#define NH    8
#define HD    64
#define BATCH 8
#define BS    (BATCH * S)      // 8192 rows

#define MASK_ELEMS (BATCH * S * S)   // 8,388,608

// MMA tiling: block 128 x BN_, 8 warps (4 along M, 2 along N)
#define BM  128
#define BK  16
#define ASTR 20                // 16 k-words + 4 pad (conflict-free frags + ldmatrix)

// ---------------------------------------------------------------------------
// Scratch (static device globals -- no allocations allowed in kernel_launch)
// ---------------------------------------------------------------------------
__device__ float g_Qraw[BS * D];             // q proj + bq (fp32, pre-round)
__device__ float g_Qu[BS * D];               // tf32(q proj + bq + u)
__device__ float g_Qv[BS * D];               // tf32(q proj + bq + v_bias)
__device__ float g_Kp[BS * D];               // tf32
__device__ float g_Vp[BS * D];               // tf32
__device__ float g_Pp[BS * D];               // tf32
__device__ float g_ctx[BS * D];              // tf32
__device__ float g_pos[67108864];            // raw pos scores [B,H,S,S] (fp32)
__device__ uchar4 g_mask4[MASK_ELEMS / 4];   // normalized mask (u8 0/1)
__device__ unsigned g_mask_kind;

// ---------------------------------------------------------------------------
// Mask dtype detection + normalization (proven correct)
// ---------------------------------------------------------------------------
__global__ void mask_detect_kernel(const unsigned* __restrict__ w)
{
    __shared__ unsigned sflags;
    if (threadIdx.x == 0) sflags = 0u;
    __syncthreads();
    unsigned f = 0u;
    for (int idx = threadIdx.x; idx < 65536; idx += blockDim.x) {
        const unsigned x = w[idx];
        if (x == 0x3F800000u)             f |= 4u;
        else if ((x & 0xFFFFFF00u) != 0u) f |= 1u;
    }
    if (f) atomicOr(&sflags, f);
    __syncthreads();
    if (threadIdx.x == 0) {
        const unsigned fl = sflags;
        g_mask_kind = (fl & 4u) ? 2u : ((fl & 1u) ? 0u : 1u);
    }
}

__global__ void mask_convert_kernel(const void* __restrict__ src)
{
    const unsigned kind = g_mask_kind;
    const int idx = blockIdx.x * blockDim.x + threadIdx.x;
    if (idx >= MASK_ELEMS / 4) return;
    uchar4 o;
    if (kind == 0u) {
        const uchar4 v = ((const uchar4*)src)[idx];
        o = make_uchar4(v.x != 0, v.y != 0, v.z != 0, v.w != 0);
    } else if (kind == 1u) {
        const int4 v = ((const int4*)src)[idx];
        o = make_uchar4(v.x != 0, v.y != 0, v.z != 0, v.w != 0);
    } else {
        const float4 v = ((const float4*)src)[idx];
        o = make_uchar4(v.x != 0.0f, v.y != 0.0f, v.z != 0.0f, v.w != 0.0f);
    }
    g_mask4[idx] = o;
}

// ---------------------------------------------------------------------------
// Async-copy, tf32, ldmatrix helpers
// ---------------------------------------------------------------------------
__device__ __forceinline__ void cp16(void* smem, const void* gmem)
{
    const unsigned s = (unsigned)__cvta_generic_to_shared(smem);
    asm volatile("cp.async.cg.shared.global [%0], [%1], 16;\n" :: "r"(s), "l"(gmem));
}
__device__ __forceinline__ void cp_commit()
{
    asm volatile("cp.async.commit_group;\n" ::: "memory");
}
__device__ __forceinline__ void cp_wait1()
{
    asm volatile("cp.async.wait_group 1;\n" ::: "memory");
}

__device__ __forceinline__ unsigned f2tf32(float x)
{
    unsigned r;
    asm("cvt.rna.tf32.f32 %0, %1;" : "=r"(r) : "f"(x));
    return r;
}
__device__ __forceinline__ float roundtf(float x)
{
    return __uint_as_float(f2tf32(x));
}

__device__ __forceinline__ void ldsm4(unsigned& r0, unsigned& r1,
                                      unsigned& r2, unsigned& r3, unsigned saddr)
{
    asm volatile("ldmatrix.sync.aligned.m8n8.x4.shared.b16 {%0,%1,%2,%3}, [%4];"
                 : "=r"(r0), "=r"(r1), "=r"(r2), "=r"(r3) : "r"(saddr));
}

__device__ __forceinline__ void mma_tf32(float* d, const unsigned* a, const unsigned* b)
{
    asm volatile(
        "mma.sync.aligned.m16n8k8.row.col.f32.tf32.tf32.f32 "
        "{%0,%1,%2,%3}, {%4,%5,%6,%7}, {%8,%9}, {%0,%1,%2,%3};\n"
        : "+f"(d[0]), "+f"(d[1]), "+f"(d[2]), "+f"(d[3])
        : "r"(a[0]), "r"(a[1]), "r"(a[2]), "r"(a[3]), "r"(b[0]), "r"(b[1]));
}

// ---------------------------------------------------------------------------
// Tensor-core GEMM core: tf32, fp32 acc, 2-stage cp.async, ldmatrix frags.
//   CVT_A/CVT_B: input values are raw fp32 -> convert in fragment path.
//                false = values already tf32-rounded (reinterpret only).
//   round_out  : round C to tf32 at store (for preconverted consumers).
// ---------------------------------------------------------------------------
template <int BN_, int NI, bool B_IS_NK, bool CVT_A, bool CVT_B>
__device__ __forceinline__ void gemm_mma(
    const float* __restrict__ A, int lda,
    const float* __restrict__ B, int ldb,
    float* __restrict__ C, int ldc, int K,
    const float* __restrict__ cbias, bool round_out)
{
    constexpr int WTN   = NI * 8;
    constexpr int BRS   = BN_ + 8;                 // NN row stride (words)
    constexpr int ATILE = BM * ASTR;
    constexpr int BTILE = B_IS_NK ? (BN_ * ASTR) : (BK * BRS);

    __shared__ float As[2][ATILE];
    __shared__ float Bs[2][BTILE];

    const int tid  = threadIdx.x;
    const int lane = tid & 31;
    const int warp = tid >> 5;
    const int g    = lane >> 2;
    const int tig  = lane & 3;
    const int wm   = (warp >> 1) * 32;
    const int wn   = (warp & 1) * WTN;

    // ldmatrix per-lane address offsets (words)
    const int grp  = lane >> 3;
    const int lr   = lane & 7;
    const int aoff = (wm + ((grp & 1) << 3) + lr) * ASTR + ((grp >> 1) << 2);
    const int boff = (wn + ((grp >> 1) << 3) + lr) * ASTR + ((grp & 1) << 2);

    float acc[2][NI][4];
    #pragma unroll
    for (int mi = 0; mi < 2; ++mi)
        #pragma unroll
        for (int ni = 0; ni < NI; ++ni)
            #pragma unroll
            for (int r = 0; r < 4; ++r) acc[mi][ni][r] = 0.0f;

    auto fill = [&](int st, int kk) {
        #pragma unroll
        for (int c = tid; c < BM * 4; c += 256) {
            const int row = c >> 2, q = c & 3;
            cp16(&As[st][row * ASTR + q * 4], A + (size_t)row * lda + kk + q * 4);
        }
        if (B_IS_NK) {
            #pragma unroll
            for (int c = tid; c < BN_ * 4; c += 256) {
                const int row = c >> 2, q = c & 3;
                cp16(&Bs[st][row * ASTR + q * 4], B + (size_t)row * ldb + kk + q * 4);
            }
        } else {
            constexpr int CPR = BN_ / 4;
            #pragma unroll
            for (int c = tid; c < BK * CPR; c += 256) {
                const int k = c / CPR, nq = c % CPR;
                cp16(&Bs[st][k * BRS + nq * 4], B + (size_t)(kk + k) * ldb + nq * 4);
            }
        }
        cp_commit();
    };

    const int T = K / BK;
    fill(0, 0);

    for (int t = 0; t < T; ++t) {
        if (t + 1 < T) fill((t + 1) & 1, (t + 1) * BK);
        else           cp_commit();
        cp_wait1();
        __syncthreads();

        const float* as = As[t & 1];
        const float* bs = Bs[t & 1];
        const unsigned as_s = (unsigned)__cvta_generic_to_shared(as);
        const unsigned bs_s = (unsigned)__cvta_generic_to_shared(bs);

        #pragma unroll
        for (int ks = 0; ks < BK; ks += 8) {
            unsigned af[2][4];
            #pragma unroll
            for (int mi = 0; mi < 2; ++mi) {
                ldsm4(af[mi][0], af[mi][1], af[mi][2], af[mi][3],
                      as_s + 4u * (aoff + mi * 16 * ASTR + ks));
                if (CVT_A) {
                    #pragma unroll
                    for (int r = 0; r < 4; ++r)
                        af[mi][r] = f2tf32(__uint_as_float(af[mi][r]));
                }
            }
            unsigned bf[NI][2];
            if (B_IS_NK) {
                #pragma unroll
                for (int np = 0; np < NI / 2; ++np) {
                    ldsm4(bf[2 * np][0], bf[2 * np][1],
                          bf[2 * np + 1][0], bf[2 * np + 1][1],
                          bs_s + 4u * (boff + np * 16 * ASTR + ks));
                }
                if (CVT_B) {
                    #pragma unroll
                    for (int ni = 0; ni < NI; ++ni) {
                        bf[ni][0] = f2tf32(__uint_as_float(bf[ni][0]));
                        bf[ni][1] = f2tf32(__uint_as_float(bf[ni][1]));
                    }
                }
            } else {
                #pragma unroll
                for (int ni = 0; ni < NI; ++ni) {
                    const float* bp = &bs[(ks + tig) * BRS + wn + ni * 8 + g];
                    if (CVT_B) {
                        bf[ni][0] = f2tf32(bp[0]);
                        bf[ni][1] = f2tf32(bp[4 * BRS]);
                    } else {
                        bf[ni][0] = __float_as_uint(bp[0]);
                        bf[ni][1] = __float_as_uint(bp[4 * BRS]);
                    }
                }
            }
            #pragma unroll
            for (int mi = 0; mi < 2; ++mi)
                #pragma unroll
                for (int ni = 0; ni < NI; ++ni)
                    mma_tf32(acc[mi][ni], af[mi], bf[ni]);
        }
        __syncthreads();
    }

    // ---- store ----
    #pragma unroll
    for (int mi = 0; mi < 2; ++mi) {
        #pragma unroll
        for (int ni = 0; ni < NI; ++ni) {
            const int r0 = wm + mi * 16 + g;
            const int c  = wn + ni * 8 + tig * 2;
            float b0 = 0.0f, b1 = 0.0f;
            if (cbias) { b0 = cbias[c]; b1 = cbias[c + 1]; }
            float v0 = acc[mi][ni][0] + b0;
            float v1 = acc[mi][ni][1] + b1;
            float v2 = acc[mi][ni][2] + b0;
            float v3 = acc[mi][ni][3] + b1;
            if (round_out) {
                v0 = roundtf(v0); v1 = roundtf(v1);
                v2 = roundtf(v2); v3 = roundtf(v3);
            }
            float* p0 = C + (size_t)r0 * ldc + c;
            float* p1 = p0 + 8 * (size_t)ldc;
            p0[0] = v0; p0[1] = v1;
            p1[0] = v2; p1[1] = v3;
        }
    }
}

// ---------------------------------------------------------------------------
// 1) Input projections. z=0: Q (raw, +bq), z=1: K, z=2: V, z=3: pos.
// ---------------------------------------------------------------------------
__global__ __launch_bounds__(256, 2)
void proj_kernel(const float* __restrict__ q, const float* __restrict__ k,
                 const float* __restrict__ v, const float* __restrict__ pe,
                 const float* __restrict__ Wq, const float* __restrict__ bq,
                 const float* __restrict__ Wk, const float* __restrict__ bk,
                 const float* __restrict__ Wv, const float* __restrict__ bv,
                 const float* __restrict__ Wpos)
{
    const size_t co = (size_t)blockIdx.y * BM * D + blockIdx.x * 128;
    if (blockIdx.z == 0) {
        gemm_mma<128, 8, true, true, true>(
            q + (size_t)blockIdx.y * BM * D, D, Wq + (size_t)blockIdx.x * 128 * D, D,
            g_Qraw + co, D, D, bq + blockIdx.x * 128, false);
    } else if (blockIdx.z == 1) {
        gemm_mma<128, 8, true, true, true>(
            k + (size_t)blockIdx.y * BM * D, D, Wk + (size_t)blockIdx.x * 128 * D, D,
            g_Kp + co, D, D, bk + blockIdx.x * 128, true);
    } else if (blockIdx.z == 2) {
        gemm_mma<128, 8, true, true, true>(
            v + (size_t)blockIdx.y * BM * D, D, Wv + (size_t)blockIdx.x * 128 * D, D,
            g_Vp + co, D, D, bv + blockIdx.x * 128, true);
    } else {
        gemm_mma<128, 8, true, true, true>(
            pe + (size_t)blockIdx.y * BM * D, D, Wpos + (size_t)blockIdx.x * 128 * D, D,
            g_Pp + co, D, D, nullptr, true);
    }
}

// g_Qu = tf32(Qraw + u); g_Qv = tf32(Qraw + vb)
__global__ __launch_bounds__(256)
void qbias_kernel(const float* __restrict__ u, const float* __restrict__ vb)
{
    const int idx = blockIdx.x * blockDim.x + threadIdx.x;     // per float4
    if (idx >= BS * D / 4) return;
    const int col4 = idx & (D / 4 - 1);
    const float4 base = ((const float4*)g_Qraw)[idx];
    const float4 u4   = ((const float4*)u)[col4];
    const float4 v4   = ((const float4*)vb)[col4];
    float4 a, bqv;
    a.x = roundtf(base.x + u4.x);  a.y = roundtf(base.y + u4.y);
    a.z = roundtf(base.z + u4.z);  a.w = roundtf(base.w + u4.w);
    bqv.x = roundtf(base.x + v4.x); bqv.y = roundtf(base.y + v4.y);
    bqv.z = roundtf(base.z + v4.z); bqv.w = roundtf(base.w + v4.w);
    ((float4*)g_Qu)[idx] = a;
    ((float4*)g_Qv)[idx] = bqv;
}

// ---------------------------------------------------------------------------
// 2) Score GEMMs (batched over b*h), NT, K=64; inputs preconverted.
// ---------------------------------------------------------------------------
__global__ __launch_bounds__(256, 2)
void score_kernel(float* __restrict__ attn_out, int which)
{
    const int bh = blockIdx.z;
    const int b  = bh >> 3;
    const int h  = bh & 7;
    const size_t head_off = (size_t)b * S * D + (size_t)h * HD;

    const float* A = (which ? g_Qv : g_Qu) + head_off + (size_t)blockIdx.y * BM * D;
    const float* B = (which ? g_Pp : g_Kp) + head_off + (size_t)blockIdx.x * 128 * D;
    float*       C = (which ? g_pos : attn_out)
                     + (size_t)bh * S * S + (size_t)blockIdx.y * BM * S + blockIdx.x * 128;
    gemm_mma<128, 8, true, false, false>(A, D, B, D, C, S, HD, nullptr, false);
}

// ---------------------------------------------------------------------------
// 3) Fused relative-shift + scale + mask + softmax
// ---------------------------------------------------------------------------
__global__ __launch_bounds__(256)
void softmax_kernel(float* __restrict__ attn)
{
    const int r  = blockIdx.x;
    const int i  = r & (S - 1);
    const int bh = r >> 10;
    const int b  = bh >> 3;

    float* row               = attn + (size_t)r * S;
    const float* prow        = g_pos + (size_t)r * S;
    const unsigned char* mrw = (const unsigned char*)g_mask4 + ((size_t)b * S + i) * S;

    const float scale = 0.04419417382415922f;   // 1/sqrt(512)
    const int tid = threadIdx.x;
    const int j0  = tid << 2;

    const float4 c4  = *(const float4*)(row + j0);
    const uchar4 m4  = *(const uchar4*)(mrw + j0);
    const float cv[4] = {c4.x, c4.y, c4.z, c4.w};
    const unsigned char mv[4] = {m4.x, m4.y, m4.z, m4.w};

    float vals[4];
    float mx = -3.4e38f;
    #pragma unroll
    for (int e = 0; e < 4; ++e) {
        const int j = j0 + e;
        float p;
        if (j <= i)          p = prow[S - 1 - i + j];
        else if (j == i + 1) p = 0.0f;
        else                 p = prow[S + j - i - 2];
        float sc = (cv[e] + p) * scale;
        if (mv[e]) sc = -10000.0f;
        vals[e] = sc;
        mx = fmaxf(mx, sc);
    }

    __shared__ float sred[8];
    __shared__ float ssum[8];

    #pragma unroll
    for (int o = 16; o; o >>= 1) mx = fmaxf(mx, __shfl_xor_sync(0xffffffffu, mx, o));
    if ((tid & 31) == 0) sred[tid >> 5] = mx;
    __syncthreads();
    if (tid < 32) {
        float v = (tid < 8) ? sred[tid] : -3.4e38f;
        #pragma unroll
        for (int o = 4; o; o >>= 1) v = fmaxf(v, __shfl_xor_sync(0xffffffffu, v, o));
        if (tid == 0) sred[0] = v;
    }
    __syncthreads();
    const float rowmax = sred[0];

    float s = 0.0f;
    #pragma unroll
    for (int e = 0; e < 4; ++e) { vals[e] = __expf(vals[e] - rowmax); s += vals[e]; }

    #pragma unroll
    for (int o = 16; o; o >>= 1) s += __shfl_xor_sync(0xffffffffu, s, o);
    if ((tid & 31) == 0) ssum[tid >> 5] = s;
    __syncthreads();
    if (tid < 32) {
        float v = (tid < 8) ? ssum[tid] : 0.0f;
        #pragma unroll
        for (int o = 4; o; o >>= 1) v += __shfl_xor_sync(0xffffffffu, v, o);
        if (tid == 0) ssum[0] = v;
    }
    __syncthreads();
    const float inv = 1.0f / ssum[0];

    float4 o4;
    o4.x = vals[0] * inv; o4.y = vals[1] * inv;
    o4.z = vals[2] * inv; o4.w = vals[3] * inv;
    *(float4*)(row + j0) = o4;
}

// ---------------------------------------------------------------------------
// 4) context = attn @ V (batched over b*h), NN, K=1024, N=64
//    A = attn (fp32 exact -> cvt), B = Vp (preconverted)
// ---------------------------------------------------------------------------
__global__ __launch_bounds__(256, 2)
void av_kernel(const float* __restrict__ attn)
{
    const int bh = blockIdx.z;
    const int b  = bh >> 3;
    const int h  = bh & 7;

    const float* A = attn + (size_t)bh * S * S + (size_t)blockIdx.y * BM * S;
    const float* B = g_Vp + (size_t)b * S * D + (size_t)h * HD;
    float*       C = g_ctx + (size_t)b * S * D + (size_t)h * HD
                     + (size_t)blockIdx.y * BM * D;
    gemm_mma<64, 4, false, true, false>(A, S, B, D, C, D, S, nullptr, true);
}

// ---------------------------------------------------------------------------
// 5) out = ctx @ Wout^T + bout ; A preconverted, B raw
// ---------------------------------------------------------------------------
__global__ __launch_bounds__(256, 2)
void outproj_kernel(const float* __restrict__ Wout, const float* __restrict__ bout,
                    float* __restrict__ out)
{
    const float* A = g_ctx + (size_t)blockIdx.y * BM * D;
    const float* B = Wout + (size_t)blockIdx.x * 128 * D;
    float*       C = out + (size_t)blockIdx.y * BM * D + blockIdx.x * 128;
    gemm_mma<128, 8, true, false, true>(A, D, B, D, C, D, D,
                                        bout + blockIdx.x * 128, false);
}

// ---------------------------------------------------------------------------
// Launch
// ---------------------------------------------------------------------------
extern "C" void kernel_launch(void* const* d_in, const int* in_sizes, int n_in,
                              void* d_out, int out_size)
{
    const float* q    = (const float*)d_in[0];
    const float* k    = (const float*)d_in[1];
    const float* v    = (const float*)d_in[2];
    const float* pe   = (const float*)d_in[3];
    const void*  mask = d_in[4];
    const float* Wq   = (const float*)d_in[5];
    const float* bq   = (const float*)d_in[6];
    const float* Wk   = (const float*)d_in[7];
    const float* bk   = (const float*)d_in[8];
    const float* Wv   = (const float*)d_in[9];
    const float* bv   = (const float*)d_in[10];
    const float* Wpos = (const float*)d_in[11];
    const float* Wout = (const float*)d_in[12];
    const float* bout = (const float*)d_in[13];
    const float* u    = (const float*)d_in[14];
    const float* vb   = (const float*)d_in[15];

    float* out_ctx  = (float*)d_out;                 // [8,1024,512]
    float* out_attn = out_ctx + (size_t)BS * D;      // [8,8,1024,1024]

    const dim3 blk(256);

    // 0) normalize mask
    mask_detect_kernel<<<1, 1024>>>((const unsigned*)mask);
    mask_convert_kernel<<<(MASK_ELEMS / 4 + 255) / 256, 256>>>(mask);

    // 1) projections (Q,K,V,P), then fold u/v_bias into Q copies (+tf32 round)
    proj_kernel<<<dim3(D / 128, BS / BM, 4), blk>>>(q, k, v, pe,
                                                    Wq, bq, Wk, bk, Wv, bv, Wpos);
    qbias_kernel<<<(BS * D / 4 + 255) / 256, 256>>>(u, vb);

    // 2) content scores -> attn region ; raw pos scores -> g_pos
    score_kernel<<<dim3(S / 128, S / BM, BATCH * NH), blk>>>(out_attn, 0);
    score_kernel<<<dim3(S / 128, S / BM, BATCH * NH), blk>>>(out_attn, 1);
    // 3) shift + scale + mask + softmax (in place)
    softmax_kernel<<<BATCH * NH * S, blk>>>(out_attn);
    // 4) context = attn @ V
    av_kernel<<<dim3(1, S / BM, BATCH * NH), blk>>>(out_attn);
    // 5) output projection
    outproj_kernel<<<dim3(D / 128, BS / BM, 1), blk>>>(Wout, bout, out_ctx);
}

// round 9
// speedup vs baseline: 3.0459x; 1.0350x over previous
#include <cuda_runtime.h>
#include <cstdint>
#include <cstddef>

// Problem constants
#define S     1024
#define D     512
#define NH    8
#define HD    64
#define BATCH 8
#define BS    (BATCH * S)      // 8192 rows

#define MASK_ELEMS (BATCH * S * S)   // 8,388,608

// MMA tiling: block 128 x BN_, 8 warps (4 along M, 2 along N)
#define BM  128
#define BK  16
#define ASTR 20                // 16 k-words + 4 pad
#define KSTR 68                // 64 k-words + 4 pad (score single-shot)
#define SCORE_SMEM_BYTES (2 * BM * KSTR * 4)   // 69,632 (dynamic)

// ---------------------------------------------------------------------------
// Scratch
// ---------------------------------------------------------------------------
__device__ float g_Qu[BS * D];               // tf32(q proj + bq + u)
__device__ float g_Qv[BS * D];               // tf32(q proj + bq + v_bias)
__device__ float g_Kp[BS * D];               // tf32
__device__ float g_Vp[BS * D];               // tf32
__device__ float g_Pp[BS * D];               // tf32
__device__ float g_ctx[BS * D];              // tf32
__device__ float g_pos[67108864];            // raw pos scores [B,H,S,S]
__device__ uchar4 g_mask4[MASK_ELEMS / 4];   // normalized mask
__device__ unsigned g_mask_kind;

// ---------------------------------------------------------------------------
// Mask dtype detection + normalization (proven)
// ---------------------------------------------------------------------------
__global__ void mask_detect_kernel(const unsigned* __restrict__ w)
{
    __shared__ unsigned sflags;
    if (threadIdx.x == 0) sflags = 0u;
    __syncthreads();
    unsigned f = 0u;
    for (int idx = threadIdx.x; idx < 65536; idx += blockDim.x) {
        const unsigned x = w[idx];
        if (x == 0x3F800000u)             f |= 4u;
        else if ((x & 0xFFFFFF00u) != 0u) f |= 1u;
    }
    if (f) atomicOr(&sflags, f);
    __syncthreads();
    if (threadIdx.x == 0) {
        const unsigned fl = sflags;
        g_mask_kind = (fl & 4u) ? 2u : ((fl & 1u) ? 0u : 1u);
    }
}

__global__ void mask_convert_kernel(const void* __restrict__ src)
{
    const unsigned kind = g_mask_kind;
    const int idx = blockIdx.x * blockDim.x + threadIdx.x;
    if (idx >= MASK_ELEMS / 4) return;
    uchar4 o;
    if (kind == 0u) {
        const uchar4 v = ((const uchar4*)src)[idx];
        o = make_uchar4(v.x != 0, v.y != 0, v.z != 0, v.w != 0);
    } else if (kind == 1u) {
        const int4 v = ((const int4*)src)[idx];
        o = make_uchar4(v.x != 0, v.y != 0, v.z != 0, v.w != 0);
    } else {
        const float4 v = ((const float4*)src)[idx];
        o = make_uchar4(v.x != 0.0f, v.y != 0.0f, v.z != 0.0f, v.w != 0.0f);
    }
    g_mask4[idx] = o;
}

// ---------------------------------------------------------------------------
// Helpers
// ---------------------------------------------------------------------------
__device__ __forceinline__ void cp16(void* smem, const void* gmem)
{
    const unsigned s = (unsigned)__cvta_generic_to_shared(smem);
    asm volatile("cp.async.cg.shared.global [%0], [%1], 16;\n" :: "r"(s), "l"(gmem));
}
__device__ __forceinline__ void cp_commit()
{
    asm volatile("cp.async.commit_group;\n" ::: "memory");
}
__device__ __forceinline__ void cp_wait1()
{
    asm volatile("cp.async.wait_group 1;\n" ::: "memory");
}
__device__ __forceinline__ void cp_wait0()
{
    asm volatile("cp.async.wait_group 0;\n" ::: "memory");
}

__device__ __forceinline__ unsigned f2tf32(float x)
{
    unsigned r;
    asm("cvt.rna.tf32.f32 %0, %1;" : "=r"(r) : "f"(x));
    return r;
}
__device__ __forceinline__ float roundtf(float x)
{
    return __uint_as_float(f2tf32(x));
}

__device__ __forceinline__ void ldsm4(unsigned& r0, unsigned& r1,
                                      unsigned& r2, unsigned& r3, unsigned saddr)
{
    asm volatile("ldmatrix.sync.aligned.m8n8.x4.shared.b16 {%0,%1,%2,%3}, [%4];"
                 : "=r"(r0), "=r"(r1), "=r"(r2), "=r"(r3) : "r"(saddr));
}

__device__ __forceinline__ void mma_tf32(float* d, const unsigned* a, const unsigned* b)
{
    asm volatile(
        "mma.sync.aligned.m16n8k8.row.col.f32.tf32.tf32.f32 "
        "{%0,%1,%2,%3}, {%4,%5,%6,%7}, {%8,%9}, {%0,%1,%2,%3};\n"
        : "+f"(d[0]), "+f"(d[1]), "+f"(d[2]), "+f"(d[3])
        : "r"(a[0]), "r"(a[1]), "r"(a[2]), "r"(a[3]), "r"(b[0]), "r"(b[1]));
}

// ---------------------------------------------------------------------------
// General GEMM core (proj / av / outproj): tf32, fp32 acc, 2-stage cp.async.
//   Optional dual output: when ub != nullptr, stores
//     C  = roundtf(acc + cbias + ub), C2 = roundtf(acc + cbias + vb2)
// ---------------------------------------------------------------------------
template <int BN_, int NI, bool B_IS_NK, bool CVT_A, bool CVT_B>
__device__ __forceinline__ void gemm_mma(
    const float* __restrict__ A, int lda,
    const float* __restrict__ B, int ldb,
    float* __restrict__ C, int ldc, int K,
    const float* __restrict__ cbias, bool round_out,
    const float* __restrict__ ub = nullptr,
    const float* __restrict__ vb2 = nullptr,
    float* __restrict__ C2 = nullptr)
{
    constexpr int WTN   = NI * 8;
    constexpr int BRS   = BN_ + 8;
    constexpr int ATILE = BM * ASTR;
    constexpr int BTILE = B_IS_NK ? (BN_ * ASTR) : (BK * BRS);

    __shared__ float As[2][ATILE];
    __shared__ float Bs[2][BTILE];

    const int tid  = threadIdx.x;
    const int lane = tid & 31;
    const int warp = tid >> 5;
    const int g    = lane >> 2;
    const int tig  = lane & 3;
    const int wm   = (warp >> 1) * 32;
    const int wn   = (warp & 1) * WTN;

    const int grp  = lane >> 3;
    const int lr   = lane & 7;
    const int aoff = (wm + ((grp & 1) << 3) + lr) * ASTR + ((grp >> 1) << 2);
    const int boff = (wn + ((grp >> 1) << 3) + lr) * ASTR + ((grp & 1) << 2);

    float acc[2][NI][4];
    #pragma unroll
    for (int mi = 0; mi < 2; ++mi)
        #pragma unroll
        for (int ni = 0; ni < NI; ++ni)
            #pragma unroll
            for (int r = 0; r < 4; ++r) acc[mi][ni][r] = 0.0f;

    auto fill = [&](int st, int kk) {
        #pragma unroll
        for (int c = tid; c < BM * 4; c += 256) {
            const int row = c >> 2, q = c & 3;
            cp16(&As[st][row * ASTR + q * 4], A + (size_t)row * lda + kk + q * 4);
        }
        if (B_IS_NK) {
            #pragma unroll
            for (int c = tid; c < BN_ * 4; c += 256) {
                const int row = c >> 2, q = c & 3;
                cp16(&Bs[st][row * ASTR + q * 4], B + (size_t)row * ldb + kk + q * 4);
            }
        } else {
            constexpr int CPR = BN_ / 4;
            #pragma unroll
            for (int c = tid; c < BK * CPR; c += 256) {
                const int k = c / CPR, nq = c % CPR;
                cp16(&Bs[st][k * BRS + nq * 4], B + (size_t)(kk + k) * ldb + nq * 4);
            }
        }
        cp_commit();
    };

    const int T = K / BK;
    fill(0, 0);

    for (int t = 0; t < T; ++t) {
        if (t + 1 < T) fill((t + 1) & 1, (t + 1) * BK);
        else           cp_commit();
        cp_wait1();
        __syncthreads();

        const float* as = As[t & 1];
        const float* bs = Bs[t & 1];
        const unsigned as_s = (unsigned)__cvta_generic_to_shared(as);
        const unsigned bs_s = (unsigned)__cvta_generic_to_shared(bs);

        #pragma unroll
        for (int ks = 0; ks < BK; ks += 8) {
            unsigned af[2][4];
            #pragma unroll
            for (int mi = 0; mi < 2; ++mi) {
                ldsm4(af[mi][0], af[mi][1], af[mi][2], af[mi][3],
                      as_s + 4u * (aoff + mi * 16 * ASTR + ks));
                if (CVT_A) {
                    #pragma unroll
                    for (int r = 0; r < 4; ++r)
                        af[mi][r] = f2tf32(__uint_as_float(af[mi][r]));
                }
            }
            unsigned bf[NI][2];
            if (B_IS_NK) {
                #pragma unroll
                for (int np = 0; np < NI / 2; ++np) {
                    ldsm4(bf[2 * np][0], bf[2 * np][1],
                          bf[2 * np + 1][0], bf[2 * np + 1][1],
                          bs_s + 4u * (boff + np * 16 * ASTR + ks));
                }
                if (CVT_B) {
                    #pragma unroll
                    for (int ni = 0; ni < NI; ++ni) {
                        bf[ni][0] = f2tf32(__uint_as_float(bf[ni][0]));
                        bf[ni][1] = f2tf32(__uint_as_float(bf[ni][1]));
                    }
                }
            } else {
                #pragma unroll
                for (int ni = 0; ni < NI; ++ni) {
                    const float* bp = &bs[(ks + tig) * BRS + wn + ni * 8 + g];
                    if (CVT_B) {
                        bf[ni][0] = f2tf32(bp[0]);
                        bf[ni][1] = f2tf32(bp[4 * BRS]);
                    } else {
                        bf[ni][0] = __float_as_uint(bp[0]);
                        bf[ni][1] = __float_as_uint(bp[4 * BRS]);
                    }
                }
            }
            #pragma unroll
            for (int mi = 0; mi < 2; ++mi)
                #pragma unroll
                for (int ni = 0; ni < NI; ++ni)
                    mma_tf32(acc[mi][ni], af[mi], bf[ni]);
        }
        __syncthreads();
    }

    // ---- store ----
    #pragma unroll
    for (int mi = 0; mi < 2; ++mi) {
        #pragma unroll
        for (int ni = 0; ni < NI; ++ni) {
            const int r0 = wm + mi * 16 + g;
            const int c  = wn + ni * 8 + tig * 2;
            float b0 = 0.0f, b1 = 0.0f;
            if (cbias) { b0 = cbias[c]; b1 = cbias[c + 1]; }
            const float s0 = acc[mi][ni][0] + b0;
            const float s1 = acc[mi][ni][1] + b1;
            const float s2 = acc[mi][ni][2] + b0;
            const float s3 = acc[mi][ni][3] + b1;
            float* p0 = C + (size_t)r0 * ldc + c;
            float* p1 = p0 + 8 * (size_t)ldc;
            if (ub) {
                const float u0 = ub[c],  u1 = ub[c + 1];
                const float w0 = vb2[c], w1 = vb2[c + 1];
                p0[0] = roundtf(s0 + u0); p0[1] = roundtf(s1 + u1);
                p1[0] = roundtf(s2 + u0); p1[1] = roundtf(s3 + u1);
                float* q0 = C2 + (size_t)r0 * ldc + c;
                float* q1 = q0 + 8 * (size_t)ldc;
                q0[0] = roundtf(s0 + w0); q0[1] = roundtf(s1 + w1);
                q1[0] = roundtf(s2 + w0); q1[1] = roundtf(s3 + w1);
            } else if (round_out) {
                p0[0] = roundtf(s0); p0[1] = roundtf(s1);
                p1[0] = roundtf(s2); p1[1] = roundtf(s3);
            } else {
                p0[0] = s0; p0[1] = s1;
                p1[0] = s2; p1[1] = s3;
            }
        }
    }
}

// ---------------------------------------------------------------------------
// 1) Input projections. z=0: Q -> dual (g_Qu, g_Qv); z=1: K; z=2: V; z=3: pos.
// ---------------------------------------------------------------------------
__global__ __launch_bounds__(256, 2)
void proj_kernel(const float* __restrict__ q, const float* __restrict__ k,
                 const float* __restrict__ v, const float* __restrict__ pe,
                 const float* __restrict__ Wq, const float* __restrict__ bq,
                 const float* __restrict__ Wk, const float* __restrict__ bk,
                 const float* __restrict__ Wv, const float* __restrict__ bv,
                 const float* __restrict__ Wpos,
                 const float* __restrict__ u, const float* __restrict__ vb)
{
    const size_t co = (size_t)blockIdx.y * BM * D + blockIdx.x * 128;
    if (blockIdx.z == 0) {
        gemm_mma<128, 8, true, true, true>(
            q + (size_t)blockIdx.y * BM * D, D, Wq + (size_t)blockIdx.x * 128 * D, D,
            g_Qu + co, D, D, bq + blockIdx.x * 128, true,
            u + blockIdx.x * 128, vb + blockIdx.x * 128, g_Qv + co);
    } else if (blockIdx.z == 1) {
        gemm_mma<128, 8, true, true, true>(
            k + (size_t)blockIdx.y * BM * D, D, Wk + (size_t)blockIdx.x * 128 * D, D,
            g_Kp + co, D, D, bk + blockIdx.x * 128, true);
    } else if (blockIdx.z == 2) {
        gemm_mma<128, 8, true, true, true>(
            v + (size_t)blockIdx.y * BM * D, D, Wv + (size_t)blockIdx.x * 128 * D, D,
            g_Vp + co, D, D, bv + blockIdx.x * 128, true);
    } else {
        gemm_mma<128, 8, true, true, true>(
            pe + (size_t)blockIdx.y * BM * D, D, Wpos + (size_t)blockIdx.x * 128 * D, D,
            g_Pp + co, D, D, nullptr, true);
    }
}

// ---------------------------------------------------------------------------
// 2) Score GEMMs, single-shot K=64, merged launch (z = which*64 + bh).
//    Uses DYNAMIC shared memory (69,632 B > 48KB static limit).
// ---------------------------------------------------------------------------
__global__ __launch_bounds__(256, 2)
void score_kernel(float* __restrict__ attn_out)
{
    extern __shared__ float smem_dyn[];
    float* As = smem_dyn;                 // BM * KSTR
    float* Bs = smem_dyn + BM * KSTR;     // 128 * KSTR

    const int which = blockIdx.z >> 6;
    const int bh    = blockIdx.z & 63;
    const int b     = bh >> 3;
    const int h     = bh & 7;
    const size_t head_off = (size_t)b * S * D + (size_t)h * HD;

    const float* A = (which ? g_Qv : g_Qu) + head_off + (size_t)blockIdx.y * BM * D;
    const float* B = (which ? g_Pp : g_Kp) + head_off + (size_t)blockIdx.x * 128 * D;
    float*       C = (which ? g_pos : attn_out)
                     + (size_t)bh * S * S + (size_t)blockIdx.y * BM * S + blockIdx.x * 128;

    const int tid  = threadIdx.x;
    const int lane = tid & 31;
    const int warp = tid >> 5;
    const int g    = lane >> 2;
    const int tig  = lane & 3;
    const int wm   = (warp >> 1) * 32;
    const int wn   = (warp & 1) * 64;

    const int grp  = lane >> 3;
    const int lr   = lane & 7;
    const int aoff = (wm + ((grp & 1) << 3) + lr) * KSTR + ((grp >> 1) << 2);
    const int boff = (wn + ((grp >> 1) << 3) + lr) * KSTR + ((grp & 1) << 2);

    // single fill: 128 rows x 64 words = 128*16 chunks each
    #pragma unroll
    for (int c = tid; c < BM * 16; c += 256) {
        const int row = c >> 4, q = c & 15;
        cp16(&As[row * KSTR + q * 4], A + (size_t)row * D + q * 4);
    }
    #pragma unroll
    for (int c = tid; c < 128 * 16; c += 256) {
        const int row = c >> 4, q = c & 15;
        cp16(&Bs[row * KSTR + q * 4], B + (size_t)row * D + q * 4);
    }
    cp_commit();
    cp_wait0();
    __syncthreads();

    const unsigned as_s = (unsigned)__cvta_generic_to_shared(As);
    const unsigned bs_s = (unsigned)__cvta_generic_to_shared(Bs);

    float acc[2][8][4];
    #pragma unroll
    for (int mi = 0; mi < 2; ++mi)
        #pragma unroll
        for (int ni = 0; ni < 8; ++ni)
            #pragma unroll
            for (int r = 0; r < 4; ++r) acc[mi][ni][r] = 0.0f;

    #pragma unroll
    for (int ks = 0; ks < HD; ks += 8) {
        unsigned af[2][4];
        #pragma unroll
        for (int mi = 0; mi < 2; ++mi)
            ldsm4(af[mi][0], af[mi][1], af[mi][2], af[mi][3],
                  as_s + 4u * (aoff + mi * 16 * KSTR + ks));
        unsigned bf[8][2];
        #pragma unroll
        for (int np = 0; np < 4; ++np)
            ldsm4(bf[2 * np][0], bf[2 * np][1], bf[2 * np + 1][0], bf[2 * np + 1][1],
                  bs_s + 4u * (boff + np * 16 * KSTR + ks));
        #pragma unroll
        for (int mi = 0; mi < 2; ++mi)
            #pragma unroll
            for (int ni = 0; ni < 8; ++ni)
                mma_tf32(acc[mi][ni], af[mi], bf[ni]);
    }

    #pragma unroll
    for (int mi = 0; mi < 2; ++mi) {
        #pragma unroll
        for (int ni = 0; ni < 8; ++ni) {
            const int r0 = wm + mi * 16 + g;
            const int c  = wn + ni * 8 + tig * 2;
            float* p0 = C + (size_t)r0 * S + c;
            float* p1 = p0 + 8 * (size_t)S;
            p0[0] = acc[mi][ni][0]; p0[1] = acc[mi][ni][1];
            p1[0] = acc[mi][ni][2]; p1[1] = acc[mi][ni][3];
        }
    }
}

// ---------------------------------------------------------------------------
// 3) Fused relative-shift + scale + mask + softmax (max-free; scores tiny)
// ---------------------------------------------------------------------------
__global__ __launch_bounds__(256)
void softmax_kernel(float* __restrict__ attn)
{
    const int r  = blockIdx.x;
    const int i  = r & (S - 1);
    const int bh = r >> 10;
    const int b  = bh >> 3;

    float* row               = attn + (size_t)r * S;
    const float* prow        = g_pos + (size_t)r * S;
    const unsigned char* mrw = (const unsigned char*)g_mask4 + ((size_t)b * S + i) * S;

    const float scale = 0.04419417382415922f;   // 1/sqrt(512)
    const int tid = threadIdx.x;
    const int j0  = tid << 2;

    const float4 c4  = *(const float4*)(row + j0);
    const uchar4 m4  = *(const uchar4*)(mrw + j0);
    const float cv[4] = {c4.x, c4.y, c4.z, c4.w};
    const unsigned char mv[4] = {m4.x, m4.y, m4.z, m4.w};

    float vals[4];
    float s = 0.0f;
    #pragma unroll
    for (int e = 0; e < 4; ++e) {
        const int j = j0 + e;
        float p;
        if (j <= i)          p = prow[S - 1 - i + j];
        else if (j == i + 1) p = 0.0f;
        else                 p = prow[S + j - i - 2];
        // scores are O(1); masked -> exactly 0 (matches exp(-1e4 - m) underflow)
        const float v = mv[e] ? 0.0f : __expf((cv[e] + p) * scale);
        vals[e] = v;
        s += v;
    }

    __shared__ float ssum[8];
    #pragma unroll
    for (int o = 16; o; o >>= 1) s += __shfl_xor_sync(0xffffffffu, s, o);
    if ((tid & 31) == 0) ssum[tid >> 5] = s;
    __syncthreads();
    if (tid < 32) {
        float v = (tid < 8) ? ssum[tid] : 0.0f;
        #pragma unroll
        for (int o = 4; o; o >>= 1) v += __shfl_xor_sync(0xffffffffu, v, o);
        if (tid == 0) ssum[0] = v;
    }
    __syncthreads();
    const float inv = 1.0f / ssum[0];

    float4 o4;
    o4.x = vals[0] * inv; o4.y = vals[1] * inv;
    o4.z = vals[2] * inv; o4.w = vals[3] * inv;
    *(float4*)(row + j0) = o4;
}

// ---------------------------------------------------------------------------
// 4) context = attn @ V (batched), NN, K=1024, N=64
// ---------------------------------------------------------------------------
__global__ __launch_bounds__(256, 2)
void av_kernel(const float* __restrict__ attn)
{
    const int bh = blockIdx.z;
    const int b  = bh >> 3;
    const int h  = bh & 7;

    const float* A = attn + (size_t)bh * S * S + (size_t)blockIdx.y * BM * S;
    const float* B = g_Vp + (size_t)b * S * D + (size_t)h * HD;
    float*       C = g_ctx + (size_t)b * S * D + (size_t)h * HD
                     + (size_t)blockIdx.y * BM * D;
    gemm_mma<64, 4, false, true, false>(A, S, B, D, C, D, S, nullptr, true);
}

// ---------------------------------------------------------------------------
// 5) out = ctx @ Wout^T + bout
// ---------------------------------------------------------------------------
__global__ __launch_bounds__(256, 2)
void outproj_kernel(const float* __restrict__ Wout, const float* __restrict__ bout,
                    float* __restrict__ out)
{
    const float* A = g_ctx + (size_t)blockIdx.y * BM * D;
    const float* B = Wout + (size_t)blockIdx.x * 128 * D;
    float*       C = out + (size_t)blockIdx.y * BM * D + blockIdx.x * 128;
    gemm_mma<128, 8, true, false, true>(A, D, B, D, C, D, D,
                                        bout + blockIdx.x * 128, false);
}

// ---------------------------------------------------------------------------
// Launch
// ---------------------------------------------------------------------------
extern "C" void kernel_launch(void* const* d_in, const int* in_sizes, int n_in,
                              void* d_out, int out_size)
{
    const float* q    = (const float*)d_in[0];
    const float* k    = (const float*)d_in[1];
    const float* v    = (const float*)d_in[2];
    const float* pe   = (const float*)d_in[3];
    const void*  mask = d_in[4];
    const float* Wq   = (const float*)d_in[5];
    const float* bq   = (const float*)d_in[6];
    const float* Wk   = (const float*)d_in[7];
    const float* bk   = (const float*)d_in[8];
    const float* Wv   = (const float*)d_in[9];
    const float* bv   = (const float*)d_in[10];
    const float* Wpos = (const float*)d_in[11];
    const float* Wout = (const float*)d_in[12];
    const float* bout = (const float*)d_in[13];
    const float* u    = (const float*)d_in[14];
    const float* vb   = (const float*)d_in[15];

    float* out_ctx  = (float*)d_out;                 // [8,1024,512]
    float* out_attn = out_ctx + (size_t)BS * D;      // [8,8,1024,1024]

    const dim3 blk(256);

    // Opt-in to >48KB dynamic smem for the score kernel (attribute set is
    // not a stream operation: runs outside capture, idempotent).
    cudaFuncSetAttribute(score_kernel,
                         cudaFuncAttributeMaxDynamicSharedMemorySize,
                         SCORE_SMEM_BYTES);

    // 0) normalize mask
    mask_detect_kernel<<<1, 1024>>>((const unsigned*)mask);
    mask_convert_kernel<<<(MASK_ELEMS / 4 + 255) / 256, 256>>>(mask);

    // 1) projections (Q dual-output with u / v_bias folded, K, V, P)
    proj_kernel<<<dim3(D / 128, BS / BM, 4), blk>>>(q, k, v, pe,
                                                    Wq, bq, Wk, bk, Wv, bv, Wpos,
                                                    u, vb);
    // 2) both score GEMMs in one launch (z<64: content -> attn, z>=64: pos -> g_pos)
    score_kernel<<<dim3(S / 128, S / BM, 2 * BATCH * NH), blk, SCORE_SMEM_BYTES>>>(out_attn);
    // 3) shift + scale + mask + softmax (in place)
    softmax_kernel<<<BATCH * NH * S, blk>>>(out_attn);
    // 4) context = attn @ V
    av_kernel<<<dim3(1, S / BM, BATCH * NH), blk>>>(out_attn);
    // 5) output projection
    outproj_kernel<<<dim3(D / 128, BS / BM, 1), blk>>>(Wout, bout, out_ctx);
}

// round 11
// speedup vs baseline: 3.4666x; 1.1381x over previous
#include <cuda_runtime.h>
#include <cuda_bf16.h>
#include <cstdint>
#include <cstddef>

// Problem constants
#define S     1024
#define D     512
#define NH    8
#define HD    64
#define BATCH 8
#define BS    (BATCH * S)      // 8192 rows

#define MASK_ELEMS (BATCH * S * S)   // 8,388,608

// MMA tiling: block 128 x BN_, 8 warps (4 along M, 2 along N)
#define BM  128
#define BK  16
#define ASTR 20                // 16 k-words + 4 pad
#define KSTR 68                // 64 k-words + 4 pad (score single-shot)
#define SCORE_SMEM_BYTES (2 * BM * KSTR * 4)   // 69,632 (dynamic)

// ---------------------------------------------------------------------------
// Scratch
// ---------------------------------------------------------------------------
__device__ float g_Qu[BS * D];               // tf32(q proj + bq + u)
__device__ float g_Qv[BS * D];               // tf32(q proj + bq + v_bias)
__device__ float g_Kp[BS * D];               // tf32
__device__ float g_Vp[BS * D];               // tf32
__device__ float g_Pp[BS * D];               // tf32
__device__ float g_ctx[BS * D];              // tf32
__device__ __nv_bfloat16 g_cs[67108864];     // content scores bf16 [B,H,S,S]
__device__ __nv_bfloat16 g_posb[67108864];   // raw pos scores bf16 [B,H,S,S]
__device__ uchar4 g_mask4[MASK_ELEMS / 4];   // normalized mask
__device__ unsigned g_mask_kind;

// ---------------------------------------------------------------------------
// Mask dtype detection + normalization (proven)
// ---------------------------------------------------------------------------
__global__ void mask_detect_kernel(const unsigned* __restrict__ w)
{
    __shared__ unsigned sflags;
    if (threadIdx.x == 0) sflags = 0u;
    __syncthreads();
    unsigned f = 0u;
    for (int idx = threadIdx.x; idx < 65536; idx += blockDim.x) {
        const unsigned x = w[idx];
        if (x == 0x3F800000u)             f |= 4u;
        else if ((x & 0xFFFFFF00u) != 0u) f |= 1u;
    }
    if (f) atomicOr(&sflags, f);
    __syncthreads();
    if (threadIdx.x == 0) {
        const unsigned fl = sflags;
        g_mask_kind = (fl & 4u) ? 2u : ((fl & 1u) ? 0u : 1u);
    }
}

__global__ void mask_convert_kernel(const void* __restrict__ src)
{
    const unsigned kind = g_mask_kind;
    const int idx = blockIdx.x * blockDim.x + threadIdx.x;
    if (idx >= MASK_ELEMS / 4) return;
    uchar4 o;
    if (kind == 0u) {
        const uchar4 v = ((const uchar4*)src)[idx];
        o = make_uchar4(v.x != 0, v.y != 0, v.z != 0, v.w != 0);
    } else if (kind == 1u) {
        const int4 v = ((const int4*)src)[idx];
        o = make_uchar4(v.x != 0, v.y != 0, v.z != 0, v.w != 0);
    } else {
        const float4 v = ((const float4*)src)[idx];
        o = make_uchar4(v.x != 0.0f, v.y != 0.0f, v.z != 0.0f, v.w != 0.0f);
    }
    g_mask4[idx] = o;
}

// ---------------------------------------------------------------------------
// Helpers
// ---------------------------------------------------------------------------
__device__ __forceinline__ void cp16(void* smem, const void* gmem)
{
    const unsigned s = (unsigned)__cvta_generic_to_shared(smem);
    asm volatile("cp.async.cg.shared.global [%0], [%1], 16;\n" :: "r"(s), "l"(gmem));
}
__device__ __forceinline__ void cp_commit()
{
    asm volatile("cp.async.commit_group;\n" ::: "memory");
}
__device__ __forceinline__ void cp_wait1()
{
    asm volatile("cp.async.wait_group 1;\n" ::: "memory");
}
__device__ __forceinline__ void cp_wait0()
{
    asm volatile("cp.async.wait_group 0;\n" ::: "memory");
}

__device__ __forceinline__ unsigned f2tf32(float x)
{
    unsigned r;
    asm("cvt.rna.tf32.f32 %0, %1;" : "=r"(r) : "f"(x));
    return r;
}
__device__ __forceinline__ float roundtf(float x)
{
    return __uint_as_float(f2tf32(x));
}

__device__ __forceinline__ void ldsm4(unsigned& r0, unsigned& r1,
                                      unsigned& r2, unsigned& r3, unsigned saddr)
{
    asm volatile("ldmatrix.sync.aligned.m8n8.x4.shared.b16 {%0,%1,%2,%3}, [%4];"
                 : "=r"(r0), "=r"(r1), "=r"(r2), "=r"(r3) : "r"(saddr));
}

__device__ __forceinline__ void mma_tf32(float* d, const unsigned* a, const unsigned* b)
{
    asm volatile(
        "mma.sync.aligned.m16n8k8.row.col.f32.tf32.tf32.f32 "
        "{%0,%1,%2,%3}, {%4,%5,%6,%7}, {%8,%9}, {%0,%1,%2,%3};\n"
        : "+f"(d[0]), "+f"(d[1]), "+f"(d[2]), "+f"(d[3])
        : "r"(a[0]), "r"(a[1]), "r"(a[2]), "r"(a[3]), "r"(b[0]), "r"(b[1]));
}

// ---------------------------------------------------------------------------
// General GEMM core (proj / av / outproj): tf32, fp32 acc, 2-stage cp.async.
//   Optional dual output: when ub != nullptr, stores
//     C  = roundtf(acc + cbias + ub), C2 = roundtf(acc + cbias + vb2)
// ---------------------------------------------------------------------------
template <int BN_, int NI, bool B_IS_NK, bool CVT_A, bool CVT_B>
__device__ __forceinline__ void gemm_mma(
    const float* __restrict__ A, int lda,
    const float* __restrict__ B, int ldb,
    float* __restrict__ C, int ldc, int K,
    const float* __restrict__ cbias, bool round_out,
    const float* __restrict__ ub = nullptr,
    const float* __restrict__ vb2 = nullptr,
    float* __restrict__ C2 = nullptr)
{
    constexpr int WTN   = NI * 8;
    constexpr int BRS   = BN_ + 8;
    constexpr int ATILE = BM * ASTR;
    constexpr int BTILE = B_IS_NK ? (BN_ * ASTR) : (BK * BRS);

    __shared__ float As[2][ATILE];
    __shared__ float Bs[2][BTILE];

    const int tid  = threadIdx.x;
    const int lane = tid & 31;
    const int warp = tid >> 5;
    const int g    = lane >> 2;
    const int tig  = lane & 3;
    const int wm   = (warp >> 1) * 32;
    const int wn   = (warp & 1) * WTN;

    const int grp  = lane >> 3;
    const int lr   = lane & 7;
    const int aoff = (wm + ((grp & 1) << 3) + lr) * ASTR + ((grp >> 1) << 2);
    const int boff = (wn + ((grp >> 1) << 3) + lr) * ASTR + ((grp & 1) << 2);

    float acc[2][NI][4];
    #pragma unroll
    for (int mi = 0; mi < 2; ++mi)
        #pragma unroll
        for (int ni = 0; ni < NI; ++ni)
            #pragma unroll
            for (int r = 0; r < 4; ++r) acc[mi][ni][r] = 0.0f;

    auto fill = [&](int st, int kk) {
        #pragma unroll
        for (int c = tid; c < BM * 4; c += 256) {
            const int row = c >> 2, q = c & 3;
            cp16(&As[st][row * ASTR + q * 4], A + (size_t)row * lda + kk + q * 4);
        }
        if (B_IS_NK) {
            #pragma unroll
            for (int c = tid; c < BN_ * 4; c += 256) {
                const int row = c >> 2, q = c & 3;
                cp16(&Bs[st][row * ASTR + q * 4], B + (size_t)row * ldb + kk + q * 4);
            }
        } else {
            constexpr int CPR = BN_ / 4;
            #pragma unroll
            for (int c = tid; c < BK * CPR; c += 256) {
                const int k = c / CPR, nq = c % CPR;
                cp16(&Bs[st][k * BRS + nq * 4], B + (size_t)(kk + k) * ldb + nq * 4);
            }
        }
        cp_commit();
    };

    const int T = K / BK;
    fill(0, 0);

    for (int t = 0; t < T; ++t) {
        if (t + 1 < T) fill((t + 1) & 1, (t + 1) * BK);
        else           cp_commit();
        cp_wait1();
        __syncthreads();

        const float* as = As[t & 1];
        const float* bs = Bs[t & 1];
        const unsigned as_s = (unsigned)__cvta_generic_to_shared(as);
        const unsigned bs_s = (unsigned)__cvta_generic_to_shared(bs);

        #pragma unroll
        for (int ks = 0; ks < BK; ks += 8) {
            unsigned af[2][4];
            #pragma unroll
            for (int mi = 0; mi < 2; ++mi) {
                ldsm4(af[mi][0], af[mi][1], af[mi][2], af[mi][3],
                      as_s + 4u * (aoff + mi * 16 * ASTR + ks));
                if (CVT_A) {
                    #pragma unroll
                    for (int r = 0; r < 4; ++r)
                        af[mi][r] = f2tf32(__uint_as_float(af[mi][r]));
                }
            }
            unsigned bf[NI][2];
            if (B_IS_NK) {
                #pragma unroll
                for (int np = 0; np < NI / 2; ++np) {
                    ldsm4(bf[2 * np][0], bf[2 * np][1],
                          bf[2 * np + 1][0], bf[2 * np + 1][1],
                          bs_s + 4u * (boff + np * 16 * ASTR + ks));
                }
                if (CVT_B) {
                    #pragma unroll
                    for (int ni = 0; ni < NI; ++ni) {
                        bf[ni][0] = f2tf32(__uint_as_float(bf[ni][0]));
                        bf[ni][1] = f2tf32(__uint_as_float(bf[ni][1]));
                    }
                }
            } else {
                #pragma unroll
                for (int ni = 0; ni < NI; ++ni) {
                    const float* bp = &bs[(ks + tig) * BRS + wn + ni * 8 + g];
                    if (CVT_B) {
                        bf[ni][0] = f2tf32(bp[0]);
                        bf[ni][1] = f2tf32(bp[4 * BRS]);
                    } else {
                        bf[ni][0] = __float_as_uint(bp[0]);
                        bf[ni][1] = __float_as_uint(bp[4 * BRS]);
                    }
                }
            }
            #pragma unroll
            for (int mi = 0; mi < 2; ++mi)
                #pragma unroll
                for (int ni = 0; ni < NI; ++ni)
                    mma_tf32(acc[mi][ni], af[mi], bf[ni]);
        }
        __syncthreads();
    }

    // ---- store ----
    #pragma unroll
    for (int mi = 0; mi < 2; ++mi) {
        #pragma unroll
        for (int ni = 0; ni < NI; ++ni) {
            const int r0 = wm + mi * 16 + g;
            const int c  = wn + ni * 8 + tig * 2;
            float b0 = 0.0f, b1 = 0.0f;
            if (cbias) { b0 = cbias[c]; b1 = cbias[c + 1]; }
            const float s0 = acc[mi][ni][0] + b0;
            const float s1 = acc[mi][ni][1] + b1;
            const float s2 = acc[mi][ni][2] + b0;
            const float s3 = acc[mi][ni][3] + b1;
            float* p0 = C + (size_t)r0 * ldc + c;
            float* p1 = p0 + 8 * (size_t)ldc;
            if (ub) {
                const float u0 = ub[c],  u1 = ub[c + 1];
                const float w0 = vb2[c], w1 = vb2[c + 1];
                p0[0] = roundtf(s0 + u0); p0[1] = roundtf(s1 + u1);
                p1[0] = roundtf(s2 + u0); p1[1] = roundtf(s3 + u1);
                float* q0 = C2 + (size_t)r0 * ldc + c;
                float* q1 = q0 + 8 * (size_t)ldc;
                q0[0] = roundtf(s0 + w0); q0[1] = roundtf(s1 + w1);
                q1[0] = roundtf(s2 + w0); q1[1] = roundtf(s3 + w1);
            } else if (round_out) {
                p0[0] = roundtf(s0); p0[1] = roundtf(s1);
                p1[0] = roundtf(s2); p1[1] = roundtf(s3);
            } else {
                p0[0] = s0; p0[1] = s1;
                p1[0] = s2; p1[1] = s3;
            }
        }
    }
}

// ---------------------------------------------------------------------------
// 1) Input projections. z=0: Q -> dual (g_Qu, g_Qv); z=1: K; z=2: V; z=3: pos.
// ---------------------------------------------------------------------------
__global__ __launch_bounds__(256, 2)
void proj_kernel(const float* __restrict__ q, const float* __restrict__ k,
                 const float* __restrict__ v, const float* __restrict__ pe,
                 const float* __restrict__ Wq, const float* __restrict__ bq,
                 const float* __restrict__ Wk, const float* __restrict__ bk,
                 const float* __restrict__ Wv, const float* __restrict__ bv,
                 const float* __restrict__ Wpos,
                 const float* __restrict__ u, const float* __restrict__ vb)
{
    const size_t co = (size_t)blockIdx.y * BM * D + blockIdx.x * 128;
    if (blockIdx.z == 0) {
        gemm_mma<128, 8, true, true, true>(
            q + (size_t)blockIdx.y * BM * D, D, Wq + (size_t)blockIdx.x * 128 * D, D,
            g_Qu + co, D, D, bq + blockIdx.x * 128, true,
            u + blockIdx.x * 128, vb + blockIdx.x * 128, g_Qv + co);
    } else if (blockIdx.z == 1) {
        gemm_mma<128, 8, true, true, true>(
            k + (size_t)blockIdx.y * BM * D, D, Wk + (size_t)blockIdx.x * 128 * D, D,
            g_Kp + co, D, D, bk + blockIdx.x * 128, true);
    } else if (blockIdx.z == 2) {
        gemm_mma<128, 8, true, true, true>(
            v + (size_t)blockIdx.y * BM * D, D, Wv + (size_t)blockIdx.x * 128 * D, D,
            g_Vp + co, D, D, bv + blockIdx.x * 128, true);
    } else {
        gemm_mma<128, 8, true, true, true>(
            pe + (size_t)blockIdx.y * BM * D, D, Wpos + (size_t)blockIdx.x * 128 * D, D,
            g_Pp + co, D, D, nullptr, true);
    }
}

// ---------------------------------------------------------------------------
// 2) Score GEMMs, single-shot K=64, merged launch (z = which*64 + bh).
//    Outputs bf16 (content -> g_cs, pos -> g_posb): halves write traffic.
// ---------------------------------------------------------------------------
__global__ __launch_bounds__(256, 2)
void score_kernel()
{
    extern __shared__ float smem_dyn[];
    float* As = smem_dyn;                 // BM * KSTR
    float* Bs = smem_dyn + BM * KSTR;     // 128 * KSTR

    const int which = blockIdx.z >> 6;
    const int bh    = blockIdx.z & 63;
    const int b     = bh >> 3;
    const int h     = bh & 7;
    const size_t head_off = (size_t)b * S * D + (size_t)h * HD;

    const float* A = (which ? g_Qv : g_Qu) + head_off + (size_t)blockIdx.y * BM * D;
    const float* B = (which ? g_Pp : g_Kp) + head_off + (size_t)blockIdx.x * 128 * D;
    __nv_bfloat16* C = (which ? g_posb : g_cs)
                       + (size_t)bh * S * S + (size_t)blockIdx.y * BM * S + blockIdx.x * 128;

    const int tid  = threadIdx.x;
    const int lane = tid & 31;
    const int warp = tid >> 5;
    const int g    = lane >> 2;
    const int tig  = lane & 3;
    const int wm   = (warp >> 1) * 32;
    const int wn   = (warp & 1) * 64;

    const int grp  = lane >> 3;
    const int lr   = lane & 7;
    const int aoff = (wm + ((grp & 1) << 3) + lr) * KSTR + ((grp >> 1) << 2);
    const int boff = (wn + ((grp >> 1) << 3) + lr) * KSTR + ((grp & 1) << 2);

    #pragma unroll
    for (int c = tid; c < BM * 16; c += 256) {
        const int row = c >> 4, q = c & 15;
        cp16(&As[row * KSTR + q * 4], A + (size_t)row * D + q * 4);
    }
    #pragma unroll
    for (int c = tid; c < 128 * 16; c += 256) {
        const int row = c >> 4, q = c & 15;
        cp16(&Bs[row * KSTR + q * 4], B + (size_t)row * D + q * 4);
    }
    cp_commit();
    cp_wait0();
    __syncthreads();

    const unsigned as_s = (unsigned)__cvta_generic_to_shared(As);
    const unsigned bs_s = (unsigned)__cvta_generic_to_shared(Bs);

    float acc[2][8][4];
    #pragma unroll
    for (int mi = 0; mi < 2; ++mi)
        #pragma unroll
        for (int ni = 0; ni < 8; ++ni)
            #pragma unroll
            for (int r = 0; r < 4; ++r) acc[mi][ni][r] = 0.0f;

    #pragma unroll
    for (int ks = 0; ks < HD; ks += 8) {
        unsigned af[2][4];
        #pragma unroll
        for (int mi = 0; mi < 2; ++mi)
            ldsm4(af[mi][0], af[mi][1], af[mi][2], af[mi][3],
                  as_s + 4u * (aoff + mi * 16 * KSTR + ks));
        unsigned bf[8][2];
        #pragma unroll
        for (int np = 0; np < 4; ++np)
            ldsm4(bf[2 * np][0], bf[2 * np][1], bf[2 * np + 1][0], bf[2 * np + 1][1],
                  bs_s + 4u * (boff + np * 16 * KSTR + ks));
        #pragma unroll
        for (int mi = 0; mi < 2; ++mi)
            #pragma unroll
            for (int ni = 0; ni < 8; ++ni)
                mma_tf32(acc[mi][ni], af[mi], bf[ni]);
    }

    #pragma unroll
    for (int mi = 0; mi < 2; ++mi) {
        #pragma unroll
        for (int ni = 0; ni < 8; ++ni) {
            const int r0 = wm + mi * 16 + g;
            const int c  = wn + ni * 8 + tig * 2;     // even
            __nv_bfloat162* p0 = (__nv_bfloat162*)(C + (size_t)r0 * S + c);
            __nv_bfloat162* p1 = (__nv_bfloat162*)(C + (size_t)(r0 + 8) * S + c);
            *p0 = __floats2bfloat162_rn(acc[mi][ni][0], acc[mi][ni][1]);
            *p1 = __floats2bfloat162_rn(acc[mi][ni][2], acc[mi][ni][3]);
        }
    }
}

// ---------------------------------------------------------------------------
// 3) Fused relative-shift + scale + mask + softmax (max-free; bf16 inputs)
//    Reads g_cs/g_posb (bf16), writes fp32 attn output.
// ---------------------------------------------------------------------------
__global__ __launch_bounds__(256)
void softmax_kernel(float* __restrict__ attn)
{
    const int r  = blockIdx.x;
    const int i  = r & (S - 1);
    const int bh = r >> 10;
    const int b  = bh >> 3;

    float* row                     = attn + (size_t)r * S;
    const __nv_bfloat16* crow      = g_cs + (size_t)r * S;
    const __nv_bfloat16* prow      = g_posb + (size_t)r * S;
    const unsigned char* mrw = (const unsigned char*)g_mask4 + ((size_t)b * S + i) * S;

    const float scale = 0.04419417382415922f;   // 1/sqrt(512)
    const int tid = threadIdx.x;
    const int j0  = tid << 2;

    const __nv_bfloat162 cA = ((const __nv_bfloat162*)crow)[tid * 2];
    const __nv_bfloat162 cB = ((const __nv_bfloat162*)crow)[tid * 2 + 1];
    const uchar4 m4  = *(const uchar4*)(mrw + j0);
    const float cv[4] = { __bfloat162float(cA.x), __bfloat162float(cA.y),
                          __bfloat162float(cB.x), __bfloat162float(cB.y) };
    const unsigned char mv[4] = {m4.x, m4.y, m4.z, m4.w};

    float vals[4];
    float s = 0.0f;
    #pragma unroll
    for (int e = 0; e < 4; ++e) {
        const int j = j0 + e;
        float p;
        if (j <= i)          p = __bfloat162float(prow[S - 1 - i + j]);
        else if (j == i + 1) p = 0.0f;
        else                 p = __bfloat162float(prow[S + j - i - 2]);
        const float v = mv[e] ? 0.0f : __expf((cv[e] + p) * scale);
        vals[e] = v;
        s += v;
    }

    __shared__ float ssum[8];
    #pragma unroll
    for (int o = 16; o; o >>= 1) s += __shfl_xor_sync(0xffffffffu, s, o);
    if ((tid & 31) == 0) ssum[tid >> 5] = s;
    __syncthreads();
    if (tid < 32) {
        float v = (tid < 8) ? ssum[tid] : 0.0f;
        #pragma unroll
        for (int o = 4; o; o >>= 1) v += __shfl_xor_sync(0xffffffffu, v, o);
        if (tid == 0) ssum[0] = v;
    }
    __syncthreads();
    const float inv = 1.0f / ssum[0];

    float4 o4;
    o4.x = vals[0] * inv; o4.y = vals[1] * inv;
    o4.z = vals[2] * inv; o4.w = vals[3] * inv;
    *(float4*)(row + j0) = o4;
}

// ---------------------------------------------------------------------------
// 4) context = attn @ V (batched), NN, K=1024, N=64
// ---------------------------------------------------------------------------
__global__ __launch_bounds__(256, 2)
void av_kernel(const float* __restrict__ attn)
{
    const int bh = blockIdx.z;
    const int b  = bh >> 3;
    const int h  = bh & 7;

    const float* A = attn + (size_t)bh * S * S + (size_t)blockIdx.y * BM * S;
    const float* B = g_Vp + (size_t)b * S * D + (size_t)h * HD;
    float*       C = g_ctx + (size_t)b * S * D + (size_t)h * HD
                     + (size_t)blockIdx.y * BM * D;
    gemm_mma<64, 4, false, true, false>(A, S, B, D, C, D, S, nullptr, true);
}

// ---------------------------------------------------------------------------
// 5) out = ctx @ Wout^T + bout
// ---------------------------------------------------------------------------
__global__ __launch_bounds__(256, 2)
void outproj_kernel(const float* __restrict__ Wout, const float* __restrict__ bout,
                    float* __restrict__ out)
{
    const float* A = g_ctx + (size_t)blockIdx.y * BM * D;
    const float* B = Wout + (size_t)blockIdx.x * 128 * D;
    float*       C = out + (size_t)blockIdx.y * BM * D + blockIdx.x * 128;
    gemm_mma<128, 8, true, false, true>(A, D, B, D, C, D, D,
                                        bout + blockIdx.x * 128, false);
}

// ---------------------------------------------------------------------------
// Launch
// ---------------------------------------------------------------------------
extern "C" void kernel_launch(void* const* d_in, const int* in_sizes, int n_in,
                              void* d_out, int out_size)
{
    const float* q    = (const float*)d_in[0];
    const float* k    = (const float*)d_in[1];
    const float* v    = (const float*)d_in[2];
    const float* pe   = (const float*)d_in[3];
    const void*  mask = d_in[4];
    const float* Wq   = (const float*)d_in[5];
    const float* bq   = (const float*)d_in[6];
    const float* Wk   = (const float*)d_in[7];
    const float* bk   = (const float*)d_in[8];
    const float* Wv   = (const float*)d_in[9];
    const float* bv   = (const float*)d_in[10];
    const float* Wpos = (const float*)d_in[11];
    const float* Wout = (const float*)d_in[12];
    const float* bout = (const float*)d_in[13];
    const float* u    = (const float*)d_in[14];
    const float* vb   = (const float*)d_in[15];

    float* out_ctx  = (float*)d_out;                 // [8,1024,512]
    float* out_attn = out_ctx + (size_t)BS * D;      // [8,8,1024,1024]

    const dim3 blk(256);

    cudaFuncSetAttribute(score_kernel,
                         cudaFuncAttributeMaxDynamicSharedMemorySize,
                         SCORE_SMEM_BYTES);

    // 0) normalize mask
    mask_detect_kernel<<<1, 1024>>>((const unsigned*)mask);
    mask_convert_kernel<<<(MASK_ELEMS / 4 + 255) / 256, 256>>>(mask);

    // 1) projections (Q dual-output with u / v_bias folded, K, V, P)
    proj_kernel<<<dim3(D / 128, BS / BM, 4), blk>>>(q, k, v, pe,
                                                    Wq, bq, Wk, bk, Wv, bv, Wpos,
                                                    u, vb);
    // 2) both score GEMMs in one launch -> bf16 intermediates
    score_kernel<<<dim3(S / 128, S / BM, 2 * BATCH * NH), blk, SCORE_SMEM_BYTES>>>();
    // 3) shift + scale + mask + softmax -> fp32 attn output
    softmax_kernel<<<BATCH * NH * S, blk>>>(out_attn);
    // 4) context = attn @ V
    av_kernel<<<dim3(1, S / BM, BATCH * NH), blk>>>(out_attn);
    // 5) output projection
    outproj_kernel<<<dim3(D / 128, BS / BM, 1), blk>>>(Wout, bout, out_ctx);
}